// round 13
// baseline (speedup 1.0000x reference)
#include <cuda_runtime.h>
#include <cuda_bf16.h>
#include <cstdint>

// Problem constants
#define BDIM  128
#define NDIM  256
#define CDIM  384
#define NHH   6
#define DDIM  64
#define TWOC  768
#define NPOS  961
#define KDIM  384                    // GEMM K (== CDIM) for all projections
#define MROWS (BDIM * NDIM)          // 32768
#define AELEM ((size_t)MROWS * CDIM) // 12,582,912

// ---------------- device scratch ----------------
__device__ float g_b1[(size_t)NHH * NDIM * NDIM];    // exp(bias1)[h][n][m]
__device__ float g_b2[(size_t)NHH * NDIM * NDIM];    // exp(bias2)[h][n][m]
__device__ float g_pos[NPOS * NHH];

// bf16 hi/lo split buffers
__device__ __nv_bfloat16 g_xh[AELEM], g_xl[AELEM];             // x1/x2 split (reused)
__device__ __nv_bfloat16 g_qvh[(size_t)MROWS * TWOC], g_qvl[(size_t)MROWS * TWOC];
__device__ __nv_bfloat16 g_kvh[(size_t)MROWS * TWOC], g_kvl[(size_t)MROWS * TWOC];
__device__ __nv_bfloat16 g_oh1[AELEM], g_ol1[AELEM];
__device__ __nv_bfloat16 g_oh2[AELEM], g_ol2[AELEM];
__device__ __nv_bfloat16 g_wh[CDIM * TWOC], g_wl[CDIM * TWOC]; // TRANSPOSED [Nc][K]

// ---------------- low-level helpers ----------------
__device__ __forceinline__ void cpa16(uint32_t dst, const void* src) {
    asm volatile("cp.async.cg.shared.global [%0], [%1], 16;\n"
                 :: "r"(dst), "l"(src));
}
__device__ __forceinline__ void ldsm_x4(uint32_t* r, uint32_t a) {
    asm volatile("ldmatrix.sync.aligned.m8n8.x4.shared.b16 {%0,%1,%2,%3}, [%4];\n"
                 : "=r"(r[0]), "=r"(r[1]), "=r"(r[2]), "=r"(r[3]) : "r"(a));
}
__device__ __forceinline__ void ldsm_x4t(uint32_t* r, uint32_t a) {
    asm volatile("ldmatrix.sync.aligned.m8n8.x4.trans.shared.b16 {%0,%1,%2,%3}, [%4];\n"
                 : "=r"(r[0]), "=r"(r[1]), "=r"(r[2]), "=r"(r[3]) : "r"(a));
}
__device__ __forceinline__ void mma16816(float* c, const uint32_t* a,
                                         const uint32_t* b) {
    asm volatile(
        "mma.sync.aligned.m16n8k16.row.col.f32.bf16.bf16.f32 "
        "{%0,%1,%2,%3}, {%4,%5,%6,%7}, {%8,%9}, {%0,%1,%2,%3};\n"
        : "+f"(c[0]), "+f"(c[1]), "+f"(c[2]), "+f"(c[3])
        : "r"(a[0]), "r"(a[1]), "r"(a[2]), "r"(a[3]), "r"(b[0]), "r"(b[1]));
}

__device__ __forceinline__ void split_store2(float a, float b,
                                             __nv_bfloat16* hi,
                                             __nv_bfloat16* lo, size_t idx)
{
    __nv_bfloat16 ha = __float2bfloat16(a), hb = __float2bfloat16(b);
    __nv_bfloat162 hp; hp.x = ha; hp.y = hb;
    *(__nv_bfloat162*)(hi + idx) = hp;
    __nv_bfloat162 lp;
    lp.x = __float2bfloat16(a - __bfloat162float(ha));
    lp.y = __float2bfloat16(b - __bfloat162float(hb));
    *(__nv_bfloat162*)(lo + idx) = lp;
}

__device__ __forceinline__ void split_pack(float p0, float p1,
                                           uint32_t& hi, uint32_t& lo)
{
    __nv_bfloat162 h = __floats2bfloat162_rn(p0, p1);
    hi = *reinterpret_cast<uint32_t*>(&h);
    __nv_bfloat162 l = __floats2bfloat162_rn(p0 - __bfloat162float(h.x),
                                             p1 - __bfloat162float(h.y));
    lo = *reinterpret_cast<uint32_t*>(&l);
}

// ---------------- tiny positional MLP ----------------
__device__ __forceinline__ void ln_relu24(const float* x, const float* g,
                                          const float* b, float* y) {
    float m = 0.f;
    #pragma unroll
    for (int p = 0; p < 24; p++) m += x[p];
    m *= (1.f / 24.f);
    float v = 0.f;
    #pragma unroll
    for (int p = 0; p < 24; p++) { float d = x[p] - m; v += d * d; }
    v *= (1.f / 24.f);
    float rs = rsqrtf(v + 1e-5f);
    #pragma unroll
    for (int p = 0; p < 24; p++) {
        float val = (x[p] - m) * rs * g[p] + b[p];
        y[p] = fmaxf(val, 0.f);
    }
}

__global__ void pos_mlp_kernel(
    const float* __restrict__ ppw, const float* __restrict__ ppb,
    const float* __restrict__ g1, const float* __restrict__ b1,
    const float* __restrict__ w1, const float* __restrict__ wb1,
    const float* __restrict__ g2, const float* __restrict__ b2,
    const float* __restrict__ w2, const float* __restrict__ wb2,
    const float* __restrict__ g3, const float* __restrict__ b3,
    const float* __restrict__ w3, const float* __restrict__ wb3)
{
    int r = blockIdx.x * blockDim.x + threadIdx.x;
    if (r >= NPOS) return;
    float ph = (float)(r / 31 - 15);
    float pw = (float)(r % 31 - 15);
    float t[24], u[24], t2[24];
    #pragma unroll
    for (int p = 0; p < 24; p++) t[p] = ph * ppw[p] + pw * ppw[24 + p] + ppb[p];
    ln_relu24(t, g1, b1, u);
    for (int q = 0; q < 24; q++) {
        float a = wb1[q];
        for (int p = 0; p < 24; p++) a += u[p] * w1[p * 24 + q];
        t2[q] = a;
    }
    ln_relu24(t2, g2, b2, u);
    for (int q = 0; q < 24; q++) {
        float a = wb2[q];
        for (int p = 0; p < 24; p++) a += u[p] * w2[p * 24 + q];
        t[q] = a;
    }
    ln_relu24(t, g3, b3, u);
    for (int q = 0; q < NHH; q++) {
        float a = wb3[q];
        for (int p = 0; p < 24; p++) a += u[p] * w3[p * NHH + q];
        g_pos[r * NHH + q] = a;
    }
}

// ---------------- bias tables (pre-exponentiated) ----------------
__global__ void bias_build_kernel(const int* __restrict__ rpi,
                                  const float* __restrict__ rpb)
{
    int t = blockIdx.x * blockDim.x + threadIdx.x;
    int h  = t >> 16;
    int nm = t & 65535;
    int r = rpi[nm];
    g_b1[t] = __expf(rpb[r * NHH + h]);
    g_b2[t] = __expf(g_pos[r * NHH + h]);
}

// ---------------- fp32 -> bf16 hi/lo split (A operands) ----------------
__global__ void split_kernel(const float* __restrict__ x,
                             __nv_bfloat16* __restrict__ hi,
                             __nv_bfloat16* __restrict__ lo, int n4)
{
    int i = blockIdx.x * blockDim.x + threadIdx.x;
    if (i >= n4) return;
    float4 v = ((const float4*)x)[i];
    __nv_bfloat16 h0 = __float2bfloat16(v.x);
    __nv_bfloat16 h1 = __float2bfloat16(v.y);
    __nv_bfloat16 h2 = __float2bfloat16(v.z);
    __nv_bfloat16 h3 = __float2bfloat16(v.w);
    __nv_bfloat162 hp0; hp0.x = h0; hp0.y = h1;
    __nv_bfloat162 hp1; hp1.x = h2; hp1.y = h3;
    ((__nv_bfloat162*)hi)[2 * i]     = hp0;
    ((__nv_bfloat162*)hi)[2 * i + 1] = hp1;
    __nv_bfloat162 lp0, lp1;
    lp0.x = __float2bfloat16(v.x - __bfloat162float(h0));
    lp0.y = __float2bfloat16(v.y - __bfloat162float(h1));
    lp1.x = __float2bfloat16(v.z - __bfloat162float(h2));
    lp1.y = __float2bfloat16(v.w - __bfloat162float(h3));
    ((__nv_bfloat162*)lo)[2 * i]     = lp0;
    ((__nv_bfloat162*)lo)[2 * i + 1] = lp1;
}

// ---------------- weight transpose-split: W[K][Nc] -> Wt hi/lo [Nc][K] ----------------
__global__ void wsplitT_kernel(const float* __restrict__ W,
                               __nv_bfloat16* __restrict__ hiT,
                               __nv_bfloat16* __restrict__ loT, int Nc)
{
    int t = blockIdx.x * blockDim.x + threadIdx.x;   // t = n*K + k
    int n = t / KDIM, k = t - n * KDIM;
    float v = W[(size_t)k * Nc + n];
    __nv_bfloat16 h = __float2bfloat16(v);
    hiT[t] = h;
    loT[t] = __float2bfloat16(v - __bfloat162float(h));
}

// ---------------- bf16x3 tensor-core GEMM (mma.sync, transposed-B) ----------------
// CTA tile 128x128, K-step 32, 8 warps (2x4), warp tile 64x32.
// INTERLEAVED mma ordering: each accumulator's 3 split-products are separated
// by 3 independent mmas (distance 4) to avoid RAW stalls on the HMMA pipe.
#define TILE_B 10240                     // bytes per tile (128 * 40 halves * 2)
#define STAGE_B (4 * TILE_B)             // 40960 bytes per stage
#define GEMM_SMEM (2 * STAGE_B)          // 81920 bytes

__global__ __launch_bounds__(256, 2) void mma_gemm_kernel(
    const __nv_bfloat16* __restrict__ Ah, const __nv_bfloat16* __restrict__ Al,
    const __nv_bfloat16* __restrict__ BhT, const __nv_bfloat16* __restrict__ BlT,
    const float* __restrict__ bias, float* __restrict__ Cf,
    __nv_bfloat16* __restrict__ Ch, __nv_bfloat16* __restrict__ Cl,
    int M, int Nc, int K, int splitOut)
{
    extern __shared__ __nv_bfloat16 sh[];
    const uint32_t sbase = (uint32_t)__cvta_generic_to_shared(sh);
    const int tid = threadIdx.x;
    const int lane = tid & 31;
    const int wid = tid >> 5;
    const int wm = wid >> 2;          // 0..1
    const int wn = wid & 3;           // 0..3
    const int rowBase = blockIdx.y * 128;
    const int colBase = blockIdx.x * 128;

    auto load_stage = [&](int s, int kt) {
        const int k0 = kt * 32;
        const uint32_t stg = sbase + s * STAGE_B;
        #pragma unroll
        for (int j = 0; j < 8; j++) {
            int idx = tid + j * 256;          // 0..2047
            int tile = idx >> 9;              // 0:Ah 1:Al 2:Bh 3:Bl
            int within = idx & 511;
            int row = within >> 2;            // 0..127
            int c8 = within & 3;              // 0..3 (8-half chunks)
            uint32_t dst = stg + tile * TILE_B + row * 80 + c8 * 16;
            const __nv_bfloat16* src;
            if (tile == 0)      src = Ah  + (size_t)(rowBase + row) * K + k0 + c8 * 8;
            else if (tile == 1) src = Al  + (size_t)(rowBase + row) * K + k0 + c8 * 8;
            else if (tile == 2) src = BhT + (size_t)(colBase + row) * K + k0 + c8 * 8;
            else                src = BlT + (size_t)(colBase + row) * K + k0 + c8 * 8;
            cpa16(dst, src);
        }
        asm volatile("cp.async.commit_group;\n");
    };

    const int NK = K >> 5;   // 12
    load_stage(0, 0);
    load_stage(1, 1);
    asm volatile("cp.async.wait_group 1;\n");
    __syncthreads();

    float acc[4][4][4] = {};

    // B ldsm lane mapping (non-trans): n row within 16-group + k half
    const int bro = ((lane >> 4) << 3) + (lane & 7);
    const int bco = ((lane >> 3) & 1) * 8;

    #pragma unroll 1
    for (int kt = 0; kt < NK; kt++) {
        const uint32_t stg = sbase + (kt & 1) * STAGE_B;
        #pragma unroll
        for (int k16 = 0; k16 < 2; k16++) {
            uint32_t bh[2][4], bl[2][4];
            #pragma unroll
            for (int np = 0; np < 2; np++) {
                uint32_t ba = stg + 2 * TILE_B +
                              (uint32_t)(wn * 32 + np * 16 + bro) * 80 +
                              (uint32_t)(k16 * 16 + bco) * 2;
                ldsm_x4(bh[np], ba);
                ldsm_x4(bl[np], ba + TILE_B);
            }
            const int acol = k16 * 16 + ((lane >> 4) << 3);
            #pragma unroll
            for (int mt = 0; mt < 4; mt++) {
                const int arow = wm * 64 + mt * 16 + (lane & 15);
                uint32_t ah[4], al[4];
                uint32_t aa = stg + (uint32_t)arow * 80 + (uint32_t)acol * 2;
                ldsm_x4(ah, aa);
                ldsm_x4(al, aa + TILE_B);
                // interleaved: same-acc mmas are distance-4 apart
                #pragma unroll
                for (int nt = 0; nt < 4; nt++)
                    mma16816(acc[mt][nt], ah, &bh[nt >> 1][(nt & 1) * 2]);
                #pragma unroll
                for (int nt = 0; nt < 4; nt++)
                    mma16816(acc[mt][nt], ah, &bl[nt >> 1][(nt & 1) * 2]);
                #pragma unroll
                for (int nt = 0; nt < 4; nt++)
                    mma16816(acc[mt][nt], al, &bh[nt >> 1][(nt & 1) * 2]);
            }
        }
        __syncthreads();
        if (kt + 2 < NK) {
            load_stage(kt & 1, kt + 2);
            asm volatile("cp.async.wait_group 1;\n");
        } else {
            asm volatile("cp.async.wait_group 0;\n");
        }
        __syncthreads();
    }

    const int g = lane >> 2, tg = lane & 3;
    #pragma unroll
    for (int mt = 0; mt < 4; mt++) {
        const int r0 = rowBase + wm * 64 + mt * 16 + g;
        #pragma unroll
        for (int nt = 0; nt < 4; nt++) {
            const int c0 = colBase + wn * 32 + nt * 8 + tg * 2;
            const float b0 = bias[c0], b1 = bias[c0 + 1];
            float v0 = acc[mt][nt][0] + b0, v1 = acc[mt][nt][1] + b1;
            float v2 = acc[mt][nt][2] + b0, v3 = acc[mt][nt][3] + b1;
            if (splitOut) {
                split_store2(v0, v1, Ch, Cl, (size_t)r0 * Nc + c0);
                split_store2(v2, v3, Ch, Cl, (size_t)(r0 + 8) * Nc + c0);
            } else {
                float2 lo = { v0, v1 };
                float2 hi = { v2, v3 };
                *(float2*)&Cf[(size_t)r0 * Nc + c0]       = lo;
                *(float2*)&Cf[(size_t)(r0 + 8) * Nc + c0] = hi;
            }
        }
    }
}

// ---------------- tensor-core dual-softmax attention ----------------
#define SQH 0
#define SQL 18432
#define SKH 36864
#define SKL 73728
#define SVH 36864
#define SVL 46080
#define ATTN_SMEM 110592

__global__ __launch_bounds__(256, 1) void attn_mma_kernel()
{
    extern __shared__ char sm[];
    const uint32_t sbase = (uint32_t)__cvta_generic_to_shared(sm);
    const int b = blockIdx.z, h = blockIdx.y, n0 = blockIdx.x * 128;
    const int tid = threadIdx.x;
    const int lane = tid & 31;
    const int wid = tid >> 5;
    const int g = lane >> 2, tg = lane & 3;
    const int i0 = wid * 16;

    {
        const __nv_bfloat16* qh = g_qvh + ((size_t)(b * NDIM + n0)) * TWOC + h * DDIM;
        const __nv_bfloat16* ql = g_qvl + ((size_t)(b * NDIM + n0)) * TWOC + h * DDIM;
        for (int idx = tid; idx < 1024; idx += 256) {
            int r = idx >> 3, c = idx & 7;
            *(uint4*)(sm + SQH + r * 144 + c * 16) = *(const uint4*)(qh + (size_t)r * TWOC + c * 8);
            *(uint4*)(sm + SQL + r * 144 + c * 16) = *(const uint4*)(ql + (size_t)r * TWOC + c * 8);
        }
        const __nv_bfloat16* kh = g_kvh + ((size_t)(b * NDIM)) * TWOC + h * DDIM;
        const __nv_bfloat16* kl = g_kvl + ((size_t)(b * NDIM)) * TWOC + h * DDIM;
        for (int idx = tid; idx < 2048; idx += 256) {
            int r = idx >> 3, c = idx & 7;
            *(uint4*)(sm + SKH + r * 144 + c * 16) = *(const uint4*)(kh + (size_t)r * TWOC + c * 8);
            *(uint4*)(sm + SKL + r * 144 + c * 16) = *(const uint4*)(kl + (size_t)r * TWOC + c * 8);
        }
    }
    __syncthreads();

    float s[32][4];
    #pragma unroll
    for (int t = 0; t < 32; t++)
        #pragma unroll
        for (int q = 0; q < 4; q++) s[t][q] = 0.f;

    const int arow = i0 + (lane & 15);
    const int krow_off = (lane & 7) + ((lane & 16) ? 8 : 0);
    #pragma unroll
    for (int d0 = 0; d0 < 64; d0 += 16) {
        uint32_t ah[4], al[4];
        const int acol = d0 + ((lane & 16) ? 8 : 0);
        ldsm_x4(ah, sbase + SQH + arow * 144 + acol * 2);
        ldsm_x4(al, sbase + SQL + arow * 144 + acol * 2);
        const int kcol = d0 + ((lane & 8) ? 8 : 0);
        // process 2 j-tiles per iteration -> 12 mmas, same-acc distance 4
        #pragma unroll
        for (int jp = 0; jp < 8; jp++) {
            uint32_t bh0[4], bl0[4], bh1[4], bl1[4];
            uint32_t ka0 = sbase + SKH + ((2 * jp) * 16 + krow_off) * 144 + kcol * 2;
            uint32_t ka1 = sbase + SKH + ((2 * jp + 1) * 16 + krow_off) * 144 + kcol * 2;
            ldsm_x4(bh0, ka0);
            ldsm_x4(bl0, ka0 + (SKL - SKH));
            ldsm_x4(bh1, ka1);
            ldsm_x4(bl1, ka1 + (SKL - SKH));
            float* s0 = s[4 * jp + 0];
            float* s1 = s[4 * jp + 1];
            float* s2 = s[4 * jp + 2];
            float* s3 = s[4 * jp + 3];
            mma16816(s0, ah, bh0);     mma16816(s1, ah, bh0 + 2);
            mma16816(s2, ah, bh1);     mma16816(s3, ah, bh1 + 2);
            mma16816(s0, ah, bl0);     mma16816(s1, ah, bl0 + 2);
            mma16816(s2, ah, bl1);     mma16816(s3, ah, bl1 + 2);
            mma16816(s0, al, bh0);     mma16816(s1, al, bh0 + 2);
            mma16816(s2, al, bh1);     mma16816(s3, al, bh1 + 2);
        }
    }

    const int rowg = n0 + i0 + g;
    const float* e1 = g_b1 + ((size_t)h * NDIM + rowg) * NDIM;
    const float* e2 = g_b2 + ((size_t)h * NDIM + rowg) * NDIM;
    float d1a = 0.f, d1b = 0.f, d2a = 0.f, d2b = 0.f;
    #pragma unroll
    for (int t = 0; t < 32; t++) {
        s[t][0] = __expf(s[t][0] * 0.125f);
        s[t][1] = __expf(s[t][1] * 0.125f);
        s[t][2] = __expf(s[t][2] * 0.125f);
        s[t][3] = __expf(s[t][3] * 0.125f);
        const int c = t * 8 + tg * 2;
        float2 e1g = *(const float2*)(e1 + c);
        float2 e1h = *(const float2*)(e1 + 8 * NDIM + c);
        float2 e2g = *(const float2*)(e2 + c);
        float2 e2h = *(const float2*)(e2 + 8 * NDIM + c);
        d1a += s[t][0] * e1g.x + s[t][1] * e1g.y;
        d1b += s[t][2] * e1h.x + s[t][3] * e1h.y;
        d2a += s[t][0] * e2g.x + s[t][1] * e2g.y;
        d2b += s[t][2] * e2h.x + s[t][3] * e2h.y;
    }
    #pragma unroll
    for (int off = 1; off <= 2; off <<= 1) {
        d1a += __shfl_xor_sync(0xffffffffu, d1a, off);
        d1b += __shfl_xor_sync(0xffffffffu, d1b, off);
        d2a += __shfl_xor_sync(0xffffffffu, d2a, off);
        d2b += __shfl_xor_sync(0xffffffffu, d2b, off);
    }
    const float r1a = 1.f / d1a, r1b = 1.f / d1b;
    const float r2a = 1.f / d2a, r2b = 1.f / d2b;

    const int vrow_off = (lane & 7) + ((lane & 8) ? 8 : 0);
    const int vcol_off = (lane & 16) ? 8 : 0;

    {
        float o1[8][4];
        #pragma unroll
        for (int nt = 0; nt < 8; nt++)
            #pragma unroll
            for (int q = 0; q < 4; q++) o1[nt][q] = 0.f;

        const __nv_bfloat16* vh = g_kvh + ((size_t)(b * NDIM)) * TWOC + CDIM + h * DDIM;
        const __nv_bfloat16* vl = g_kvl + ((size_t)(b * NDIM)) * TWOC + CDIM + h * DDIM;
        #pragma unroll
        for (int chunk = 0; chunk < 4; chunk++) {
            __syncthreads();
            for (int idx = tid; idx < 512; idx += 256) {
                int r = idx >> 3, c = idx & 7;
                size_t gr = (size_t)(chunk * 64 + r) * TWOC + c * 8;
                *(uint4*)(sm + SVH + r * 144 + c * 16) = *(const uint4*)(vh + gr);
                *(uint4*)(sm + SVL + r * 144 + c * 16) = *(const uint4*)(vl + gr);
            }
            __syncthreads();
            #pragma unroll
            for (int kk = 0; kk < 4; kk++) {
                const int t0 = chunk * 8 + kk * 2;
                const int ca = t0 * 8 + tg * 2;
                float2 eA = *(const float2*)(e1 + ca);
                float2 eB = *(const float2*)(e1 + 8 * NDIM + ca);
                float2 eC = *(const float2*)(e1 + ca + 8);
                float2 eD = *(const float2*)(e1 + 8 * NDIM + ca + 8);
                uint32_t pH[4], pL[4];
                split_pack(s[t0][0] * eA.x * r1a,     s[t0][1] * eA.y * r1a,     pH[0], pL[0]);
                split_pack(s[t0][2] * eB.x * r1b,     s[t0][3] * eB.y * r1b,     pH[1], pL[1]);
                split_pack(s[t0 + 1][0] * eC.x * r1a, s[t0 + 1][1] * eC.y * r1a, pH[2], pL[2]);
                split_pack(s[t0 + 1][2] * eD.x * r1b, s[t0 + 1][3] * eD.y * r1b, pH[3], pL[3]);
                const int vrow = kk * 16 + vrow_off;
                // process 2 d-tiles per iteration -> same-acc distance 4
                #pragma unroll
                for (int dp = 0; dp < 2; dp++) {
                    uint32_t bh0[4], bl0[4], bh1[4], bl1[4];
                    uint32_t va0 = sbase + SVH + vrow * 144 + ((2 * dp) * 16 + vcol_off) * 2;
                    uint32_t va1 = sbase + SVH + vrow * 144 + ((2 * dp + 1) * 16 + vcol_off) * 2;
                    ldsm_x4t(bh0, va0);
                    ldsm_x4t(bl0, va0 + (SVL - SVH));
                    ldsm_x4t(bh1, va1);
                    ldsm_x4t(bl1, va1 + (SVL - SVH));
                    float* o0 = o1[4 * dp + 0];
                    float* oA = o1[4 * dp + 1];
                    float* oB = o1[4 * dp + 2];
                    float* oC = o1[4 * dp + 3];
                    mma16816(o0, pH, bh0);     mma16816(oA, pH, bh0 + 2);
                    mma16816(oB, pH, bh1);     mma16816(oC, pH, bh1 + 2);
                    mma16816(o0, pH, bl0);     mma16816(oA, pH, bl0 + 2);
                    mma16816(oB, pH, bl1);     mma16816(oC, pH, bl1 + 2);
                    mma16816(o0, pL, bh0);     mma16816(oA, pL, bh0 + 2);
                    mma16816(oB, pL, bh1);     mma16816(oC, pL, bh1 + 2);
                }
            }
        }
        const size_t orow = (size_t)(b * NDIM + n0 + i0 + g);
        #pragma unroll
        for (int nt = 0; nt < 8; nt++) {
            const int col = h * DDIM + nt * 8 + tg * 2;
            split_store2(o1[nt][0], o1[nt][1], g_oh1, g_ol1, orow * CDIM + col);
            split_store2(o1[nt][2], o1[nt][3], g_oh1, g_ol1, (orow + 8) * CDIM + col);
        }
    }

    {
        float o2[8][4];
        #pragma unroll
        for (int nt = 0; nt < 8; nt++)
            #pragma unroll
            for (int q = 0; q < 4; q++) o2[nt][q] = 0.f;

        const __nv_bfloat16* vh = g_qvh + ((size_t)(b * NDIM)) * TWOC + CDIM + h * DDIM;
        const __nv_bfloat16* vl = g_qvl + ((size_t)(b * NDIM)) * TWOC + CDIM + h * DDIM;
        #pragma unroll
        for (int chunk = 0; chunk < 4; chunk++) {
            __syncthreads();
            for (int idx = tid; idx < 512; idx += 256) {
                int r = idx >> 3, c = idx & 7;
                size_t gr = (size_t)(chunk * 64 + r) * TWOC + c * 8;
                *(uint4*)(sm + SVH + r * 144 + c * 16) = *(const uint4*)(vh + gr);
                *(uint4*)(sm + SVL + r * 144 + c * 16) = *(const uint4*)(vl + gr);
            }
            __syncthreads();
            #pragma unroll
            for (int kk = 0; kk < 4; kk++) {
                const int t0 = chunk * 8 + kk * 2;
                const int ca = t0 * 8 + tg * 2;
                float2 eA = *(const float2*)(e2 + ca);
                float2 eB = *(const float2*)(e2 + 8 * NDIM + ca);
                float2 eC = *(const float2*)(e2 + ca + 8);
                float2 eD = *(const float2*)(e2 + 8 * NDIM + ca + 8);
                uint32_t pH[4], pL[4];
                split_pack(s[t0][0] * eA.x * r2a,     s[t0][1] * eA.y * r2a,     pH[0], pL[0]);
                split_pack(s[t0][2] * eB.x * r2b,     s[t0][3] * eB.y * r2b,     pH[1], pL[1]);
                split_pack(s[t0 + 1][0] * eC.x * r2a, s[t0 + 1][1] * eC.y * r2a, pH[2], pL[2]);
                split_pack(s[t0 + 1][2] * eD.x * r2b, s[t0 + 1][3] * eD.y * r2b, pH[3], pL[3]);
                const int vrow = kk * 16 + vrow_off;
                #pragma unroll
                for (int dp = 0; dp < 2; dp++) {
                    uint32_t bh0[4], bl0[4], bh1[4], bl1[4];
                    uint32_t va0 = sbase + SVH + vrow * 144 + ((2 * dp) * 16 + vcol_off) * 2;
                    uint32_t va1 = sbase + SVH + vrow * 144 + ((2 * dp + 1) * 16 + vcol_off) * 2;
                    ldsm_x4t(bh0, va0);
                    ldsm_x4t(bl0, va0 + (SVL - SVH));
                    ldsm_x4t(bh1, va1);
                    ldsm_x4t(bl1, va1 + (SVL - SVH));
                    float* o0 = o2[4 * dp + 0];
                    float* oA = o2[4 * dp + 1];
                    float* oB = o2[4 * dp + 2];
                    float* oC = o2[4 * dp + 3];
                    mma16816(o0, pH, bh0);     mma16816(oA, pH, bh0 + 2);
                    mma16816(oB, pH, bh1);     mma16816(oC, pH, bh1 + 2);
                    mma16816(o0, pH, bl0);     mma16816(oA, pH, bl0 + 2);
                    mma16816(oB, pH, bl1);     mma16816(oC, pH, bl1 + 2);
                    mma16816(o0, pL, bh0);     mma16816(oA, pL, bh0 + 2);
                    mma16816(oB, pL, bh1);     mma16816(oC, pL, bh1 + 2);
                }
            }
        }
        const size_t orow = (size_t)(b * NDIM + n0 + i0 + g);
        #pragma unroll
        for (int nt = 0; nt < 8; nt++) {
            const int col = h * DDIM + nt * 8 + tg * 2;
            split_store2(o2[nt][0], o2[nt][1], g_oh2, g_ol2, orow * CDIM + col);
            split_store2(o2[nt][2], o2[nt][3], g_oh2, g_ol2, (orow + 8) * CDIM + col);
        }
    }
}

// ---------------- launch ----------------
extern "C" void kernel_launch(void* const* d_in, const int* in_sizes, int n_in,
                              void* d_out, int out_size)
{
    const float* x1    = (const float*)d_in[0];
    const float* x2    = (const float*)d_in[1];
    const float* qv_w  = (const float*)d_in[2];
    const float* qv_b  = (const float*)d_in[3];
    const float* kv_w  = (const float*)d_in[4];
    const float* kv_b  = (const float*)d_in[5];
    const float* p1w   = (const float*)d_in[6];
    const float* p1b   = (const float*)d_in[7];
    const float* p2w   = (const float*)d_in[8];
    const float* p2b   = (const float*)d_in[9];
    const float* rpb   = (const float*)d_in[10];
    const float* ppw   = (const float*)d_in[11];
    const float* ppb   = (const float*)d_in[12];
    const float* ln1g  = (const float*)d_in[13];
    const float* ln1b  = (const float*)d_in[14];
    const float* l1w   = (const float*)d_in[15];
    const float* l1b   = (const float*)d_in[16];
    const float* ln2g  = (const float*)d_in[17];
    const float* ln2b  = (const float*)d_in[18];
    const float* l2w   = (const float*)d_in[19];
    const float* l2b   = (const float*)d_in[20];
    const float* ln3g  = (const float*)d_in[21];
    const float* ln3b  = (const float*)d_in[22];
    const float* l3w   = (const float*)d_in[23];
    const float* l3b   = (const float*)d_in[24];
    const int*   rpi   = (const int*)d_in[25];
    float* out = (float*)d_out;

    __nv_bfloat16 *pxh, *pxl, *pwh, *pwl;
    __nv_bfloat16 *pqvh, *pqvl, *pkvh, *pkvl;
    __nv_bfloat16 *poh1, *pol1, *poh2, *pol2;
    cudaGetSymbolAddress((void**)&pxh, g_xh);
    cudaGetSymbolAddress((void**)&pxl, g_xl);
    cudaGetSymbolAddress((void**)&pwh, g_wh);
    cudaGetSymbolAddress((void**)&pwl, g_wl);
    cudaGetSymbolAddress((void**)&pqvh, g_qvh);
    cudaGetSymbolAddress((void**)&pqvl, g_qvl);
    cudaGetSymbolAddress((void**)&pkvh, g_kvh);
    cudaGetSymbolAddress((void**)&pkvl, g_kvl);
    cudaGetSymbolAddress((void**)&poh1, g_oh1);
    cudaGetSymbolAddress((void**)&pol1, g_ol1);
    cudaGetSymbolAddress((void**)&poh2, g_oh2);
    cudaGetSymbolAddress((void**)&pol2, g_ol2);

    cudaFuncSetAttribute(mma_gemm_kernel,
                         cudaFuncAttributeMaxDynamicSharedMemorySize, GEMM_SMEM);
    cudaFuncSetAttribute(attn_mma_kernel,
                         cudaFuncAttributeMaxDynamicSharedMemorySize, ATTN_SMEM);

    const int X4 = (int)(AELEM / 4);

    // 1) positional MLP + pre-exponentiated bias tables
    pos_mlp_kernel<<<4, 256>>>(ppw, ppb, ln1g, ln1b, l1w, l1b,
                               ln2g, ln2b, l2w, l2b, ln3g, ln3b, l3w, l3b);
    bias_build_kernel<<<(NHH * NDIM * NDIM) / 256, 256>>>(rpi, rpb);

    // 2) QV projection -> bf16 hi/lo
    split_kernel<<<X4 / 256, 256>>>(x1, pxh, pxl, X4);
    wsplitT_kernel<<<(TWOC * KDIM) / 256, 256>>>(qv_w, pwh, pwl, TWOC);
    mma_gemm_kernel<<<dim3(TWOC / 128, MROWS / 128), 256, GEMM_SMEM>>>(
        pxh, pxl, pwh, pwl, qv_b, nullptr, pqvh, pqvl, MROWS, TWOC, KDIM, 1);

    // 3) KV projection -> bf16 hi/lo
    split_kernel<<<X4 / 256, 256>>>(x2, pxh, pxl, X4);
    wsplitT_kernel<<<(TWOC * KDIM) / 256, 256>>>(kv_w, pwh, pwl, TWOC);
    mma_gemm_kernel<<<dim3(TWOC / 128, MROWS / 128), 256, GEMM_SMEM>>>(
        pxh, pxl, pwh, pwl, kv_b, nullptr, pkvh, pkvl, MROWS, TWOC, KDIM, 1);

    // 4) tensor-core dual-softmax attention (bf16 hi/lo outputs)
    attn_mma_kernel<<<dim3(NDIM / 128, NHH, BDIM), 256, ATTN_SMEM>>>();

    // 5) output projections into d_out (fp32)
    wsplitT_kernel<<<(CDIM * KDIM) / 256, 256>>>(p1w, pwh, pwl, CDIM);
    mma_gemm_kernel<<<dim3(CDIM / 128, MROWS / 128), 256, GEMM_SMEM>>>(
        poh1, pol1, pwh, pwl, p1b, out, nullptr, nullptr, MROWS, CDIM, KDIM, 0);
    wsplitT_kernel<<<(CDIM * KDIM) / 256, 256>>>(p2w, pwh, pwl, CDIM);
    mma_gemm_kernel<<<dim3(CDIM / 128, MROWS / 128), 256, GEMM_SMEM>>>(
        poh2, pol2, pwh, pwl, p2b, out + AELEM, nullptr, nullptr, MROWS, CDIM, KDIM, 0);
}

// round 14
// speedup vs baseline: 1.6655x; 1.6655x over previous
#include <cuda_runtime.h>
#include <cuda_fp16.h>
#include <cstdint>

// Problem constants
#define BDIM  128
#define NDIM  256
#define CDIM  384
#define NHH   6
#define DDIM  64
#define TWOC  768
#define NPOS  961
#define KDIM  384                    // GEMM K (== CDIM) for all projections
#define MROWS (BDIM * NDIM)          // 32768
#define AELEM ((size_t)MROWS * CDIM) // 12,582,912

// ---------------- device scratch ----------------
__device__ float g_b1[(size_t)NHH * NDIM * NDIM];    // exp(bias1)[h][n][m]
__device__ float g_b2[(size_t)NHH * NDIM * NDIM];    // exp(bias2)[h][n][m]
__device__ float g_pos[NPOS * NHH];

// fp16 buffers (single precision products, fp32 accumulate)
__device__ __half g_x[AELEM];                        // x1/x2 convert (reused)
__device__ __half g_w[CDIM * TWOC];                  // weights TRANSPOSED [Nc][K]
__device__ __half g_qv[(size_t)MROWS * TWOC];
__device__ __half g_kv[(size_t)MROWS * TWOC];
__device__ __half g_o1[AELEM], g_o2[AELEM];

// ---------------- low-level helpers ----------------
__device__ __forceinline__ void cpa16(uint32_t dst, const void* src) {
    asm volatile("cp.async.cg.shared.global [%0], [%1], 16;\n"
                 :: "r"(dst), "l"(src));
}
__device__ __forceinline__ void ldsm_x4(uint32_t* r, uint32_t a) {
    asm volatile("ldmatrix.sync.aligned.m8n8.x4.shared.b16 {%0,%1,%2,%3}, [%4];\n"
                 : "=r"(r[0]), "=r"(r[1]), "=r"(r[2]), "=r"(r[3]) : "r"(a));
}
__device__ __forceinline__ void ldsm_x4t(uint32_t* r, uint32_t a) {
    asm volatile("ldmatrix.sync.aligned.m8n8.x4.trans.shared.b16 {%0,%1,%2,%3}, [%4];\n"
                 : "=r"(r[0]), "=r"(r[1]), "=r"(r[2]), "=r"(r[3]) : "r"(a));
}
__device__ __forceinline__ void mma16816(float* c, const uint32_t* a,
                                         const uint32_t* b) {
    asm volatile(
        "mma.sync.aligned.m16n8k16.row.col.f32.f16.f16.f32 "
        "{%0,%1,%2,%3}, {%4,%5,%6,%7}, {%8,%9}, {%0,%1,%2,%3};\n"
        : "+f"(c[0]), "+f"(c[1]), "+f"(c[2]), "+f"(c[3])
        : "r"(a[0]), "r"(a[1]), "r"(a[2]), "r"(a[3]), "r"(b[0]), "r"(b[1]));
}
__device__ __forceinline__ uint32_t pack_h2(float a, float b) {
    __half2 h = __floats2half2_rn(a, b);   // .x = a (low half)
    return *reinterpret_cast<uint32_t*>(&h);
}

// ---------------- tiny positional MLP ----------------
__device__ __forceinline__ void ln_relu24(const float* x, const float* g,
                                          const float* b, float* y) {
    float m = 0.f;
    #pragma unroll
    for (int p = 0; p < 24; p++) m += x[p];
    m *= (1.f / 24.f);
    float v = 0.f;
    #pragma unroll
    for (int p = 0; p < 24; p++) { float d = x[p] - m; v += d * d; }
    v *= (1.f / 24.f);
    float rs = rsqrtf(v + 1e-5f);
    #pragma unroll
    for (int p = 0; p < 24; p++) {
        float val = (x[p] - m) * rs * g[p] + b[p];
        y[p] = fmaxf(val, 0.f);
    }
}

__global__ void pos_mlp_kernel(
    const float* __restrict__ ppw, const float* __restrict__ ppb,
    const float* __restrict__ g1, const float* __restrict__ b1,
    const float* __restrict__ w1, const float* __restrict__ wb1,
    const float* __restrict__ g2, const float* __restrict__ b2,
    const float* __restrict__ w2, const float* __restrict__ wb2,
    const float* __restrict__ g3, const float* __restrict__ b3,
    const float* __restrict__ w3, const float* __restrict__ wb3)
{
    int r = blockIdx.x * blockDim.x + threadIdx.x;
    if (r >= NPOS) return;
    float ph = (float)(r / 31 - 15);
    float pw = (float)(r % 31 - 15);
    float t[24], u[24], t2[24];
    #pragma unroll
    for (int p = 0; p < 24; p++) t[p] = ph * ppw[p] + pw * ppw[24 + p] + ppb[p];
    ln_relu24(t, g1, b1, u);
    for (int q = 0; q < 24; q++) {
        float a = wb1[q];
        for (int p = 0; p < 24; p++) a += u[p] * w1[p * 24 + q];
        t2[q] = a;
    }
    ln_relu24(t2, g2, b2, u);
    for (int q = 0; q < 24; q++) {
        float a = wb2[q];
        for (int p = 0; p < 24; p++) a += u[p] * w2[p * 24 + q];
        t[q] = a;
    }
    ln_relu24(t, g3, b3, u);
    for (int q = 0; q < NHH; q++) {
        float a = wb3[q];
        for (int p = 0; p < 24; p++) a += u[p] * w3[p * NHH + q];
        g_pos[r * NHH + q] = a;
    }
}

// ---------------- bias tables (pre-exponentiated) ----------------
__global__ void bias_build_kernel(const int* __restrict__ rpi,
                                  const float* __restrict__ rpb)
{
    int t = blockIdx.x * blockDim.x + threadIdx.x;
    int h  = t >> 16;
    int nm = t & 65535;
    int r = rpi[nm];
    g_b1[t] = __expf(rpb[r * NHH + h]);
    g_b2[t] = __expf(g_pos[r * NHH + h]);
}

// ---------------- fp32 -> fp16 convert ----------------
__global__ void conv_kernel(const float* __restrict__ x,
                            __half* __restrict__ y, int n4)
{
    int i = blockIdx.x * blockDim.x + threadIdx.x;
    if (i >= n4) return;
    float4 v = ((const float4*)x)[i];
    ((__half2*)y)[2 * i]     = __floats2half2_rn(v.x, v.y);
    ((__half2*)y)[2 * i + 1] = __floats2half2_rn(v.z, v.w);
}

// ---------------- weight transpose-convert: W[K][Nc] -> Wt [Nc][K] ----------------
__global__ void wconvT_kernel(const float* __restrict__ W,
                              __half* __restrict__ yT, int Nc)
{
    int t = blockIdx.x * blockDim.x + threadIdx.x;   // t = n*K + k
    int n = t / KDIM, k = t - n * KDIM;
    yT[t] = __float2half(W[(size_t)k * Nc + n]);
}

// ---------------- fp16 tensor-core GEMM (mma.sync, transposed-B) ----------------
// CTA tile 128x128, K-step 32, 8 warps (2x4), warp tile 64x32.
// Tiles (A and BT) are 128 rows x 32 halves, stride 40 halves.
#define TILE_B 10240                     // bytes per tile (128 * 40 halves * 2)
#define STAGE_B (2 * TILE_B)             // 20480 bytes per stage
#define GEMM_SMEM (2 * STAGE_B)          // 40960 bytes

__global__ __launch_bounds__(256, 2) void mma_gemm_kernel(
    const __half* __restrict__ A, const __half* __restrict__ BT,
    const float* __restrict__ bias, float* __restrict__ Cf,
    __half* __restrict__ Ch, int M, int Nc, int K, int halfOut)
{
    extern __shared__ __half sh[];
    const uint32_t sbase = (uint32_t)__cvta_generic_to_shared(sh);
    const int tid = threadIdx.x;
    const int lane = tid & 31;
    const int wid = tid >> 5;
    const int wm = wid >> 2;          // 0..1
    const int wn = wid & 3;           // 0..3
    const int rowBase = blockIdx.y * 128;
    const int colBase = blockIdx.x * 128;

    auto load_stage = [&](int s, int kt) {
        const int k0 = kt * 32;
        const uint32_t stg = sbase + s * STAGE_B;
        #pragma unroll
        for (int j = 0; j < 4; j++) {
            int idx = tid + j * 256;          // 0..1023
            int tile = idx >> 9;              // 0:A 1:BT
            int within = idx & 511;
            int row = within >> 2;            // 0..127
            int c8 = within & 3;              // 0..3 (8-half chunks)
            uint32_t dst = stg + tile * TILE_B + row * 80 + c8 * 16;
            const __half* src = (tile == 0)
                ? A  + (size_t)(rowBase + row) * K + k0 + c8 * 8
                : BT + (size_t)(colBase + row) * K + k0 + c8 * 8;
            cpa16(dst, src);
        }
        asm volatile("cp.async.commit_group;\n");
    };

    const int NK = K >> 5;   // 12
    load_stage(0, 0);
    load_stage(1, 1);
    asm volatile("cp.async.wait_group 1;\n");
    __syncthreads();

    float acc[4][4][4] = {};

    // B ldsm lane mapping (non-trans): n row within 16-group + k half
    const int bro = ((lane >> 4) << 3) + (lane & 7);
    const int bco = ((lane >> 3) & 1) * 8;

    #pragma unroll 1
    for (int kt = 0; kt < NK; kt++) {
        const uint32_t stg = sbase + (kt & 1) * STAGE_B;
        #pragma unroll
        for (int k16 = 0; k16 < 2; k16++) {
            uint32_t bfr[2][4];
            #pragma unroll
            for (int np = 0; np < 2; np++) {
                uint32_t ba = stg + TILE_B +
                              (uint32_t)(wn * 32 + np * 16 + bro) * 80 +
                              (uint32_t)(k16 * 16 + bco) * 2;
                ldsm_x4(bfr[np], ba);
            }
            const int acol = k16 * 16 + ((lane >> 4) << 3);
            #pragma unroll
            for (int mt = 0; mt < 4; mt++) {
                const int arow = wm * 64 + mt * 16 + (lane & 15);
                uint32_t a[4];
                ldsm_x4(a, stg + (uint32_t)arow * 80 + (uint32_t)acol * 2);
                #pragma unroll
                for (int nt = 0; nt < 4; nt++)
                    mma16816(acc[mt][nt], a, &bfr[nt >> 1][(nt & 1) * 2]);
            }
        }
        __syncthreads();
        if (kt + 2 < NK) {
            load_stage(kt & 1, kt + 2);
            asm volatile("cp.async.wait_group 1;\n");
        } else {
            asm volatile("cp.async.wait_group 0;\n");
        }
        __syncthreads();
    }

    const int g = lane >> 2, tg = lane & 3;
    #pragma unroll
    for (int mt = 0; mt < 4; mt++) {
        const int r0 = rowBase + wm * 64 + mt * 16 + g;
        #pragma unroll
        for (int nt = 0; nt < 4; nt++) {
            const int c0 = colBase + wn * 32 + nt * 8 + tg * 2;
            const float b0 = bias[c0], b1 = bias[c0 + 1];
            float v0 = acc[mt][nt][0] + b0, v1 = acc[mt][nt][1] + b1;
            float v2 = acc[mt][nt][2] + b0, v3 = acc[mt][nt][3] + b1;
            if (halfOut) {
                *(__half2*)&Ch[(size_t)r0 * Nc + c0]       = __floats2half2_rn(v0, v1);
                *(__half2*)&Ch[(size_t)(r0 + 8) * Nc + c0] = __floats2half2_rn(v2, v3);
            } else {
                float2 lo = { v0, v1 };
                float2 hi = { v2, v3 };
                *(float2*)&Cf[(size_t)r0 * Nc + c0]       = lo;
                *(float2*)&Cf[(size_t)(r0 + 8) * Nc + c0] = hi;
            }
        }
    }
}

// ---------------- fp16 tensor-core dual-softmax attention ----------------
// smem: Q 128x64 halves (stride 144B) at 0; K 256x64 at 18432; V chunks overlay K.
#define SQ 0
#define SK 18432
#define SV 18432
#define ATTN_SMEM 55296

__global__ __launch_bounds__(256, 1) void attn_mma_kernel()
{
    extern __shared__ char sm[];
    const uint32_t sbase = (uint32_t)__cvta_generic_to_shared(sm);
    const int b = blockIdx.z, h = blockIdx.y, n0 = blockIdx.x * 128;
    const int tid = threadIdx.x;
    const int lane = tid & 31;
    const int wid = tid >> 5;
    const int g = lane >> 2, tg = lane & 3;
    const int i0 = wid * 16;

    {
        const __half* q = g_qv + ((size_t)(b * NDIM + n0)) * TWOC + h * DDIM;
        for (int idx = tid; idx < 1024; idx += 256) {
            int r = idx >> 3, c = idx & 7;
            *(uint4*)(sm + SQ + r * 144 + c * 16) = *(const uint4*)(q + (size_t)r * TWOC + c * 8);
        }
        const __half* k = g_kv + ((size_t)(b * NDIM)) * TWOC + h * DDIM;
        for (int idx = tid; idx < 2048; idx += 256) {
            int r = idx >> 3, c = idx & 7;
            *(uint4*)(sm + SK + r * 144 + c * 16) = *(const uint4*)(k + (size_t)r * TWOC + c * 8);
        }
    }
    __syncthreads();

    float s[32][4];
    #pragma unroll
    for (int t = 0; t < 32; t++)
        #pragma unroll
        for (int q = 0; q < 4; q++) s[t][q] = 0.f;

    const int arow = i0 + (lane & 15);
    const int krow_off = (lane & 7) + ((lane & 16) ? 8 : 0);
    #pragma unroll
    for (int d0 = 0; d0 < 64; d0 += 16) {
        uint32_t a[4];
        const int acol = d0 + ((lane & 16) ? 8 : 0);
        ldsm_x4(a, sbase + SQ + arow * 144 + acol * 2);
        const int kcol = d0 + ((lane & 8) ? 8 : 0);
        #pragma unroll
        for (int jp = 0; jp < 8; jp++) {
            uint32_t b0[4], b1[4];
            ldsm_x4(b0, sbase + SK + ((2 * jp) * 16 + krow_off) * 144 + kcol * 2);
            ldsm_x4(b1, sbase + SK + ((2 * jp + 1) * 16 + krow_off) * 144 + kcol * 2);
            mma16816(s[4 * jp + 0], a, b0);
            mma16816(s[4 * jp + 1], a, b0 + 2);
            mma16816(s[4 * jp + 2], a, b1);
            mma16816(s[4 * jp + 3], a, b1 + 2);
        }
    }

    const int rowg = n0 + i0 + g;
    const float* e1 = g_b1 + ((size_t)h * NDIM + rowg) * NDIM;
    const float* e2 = g_b2 + ((size_t)h * NDIM + rowg) * NDIM;
    float d1a = 0.f, d1b = 0.f, d2a = 0.f, d2b = 0.f;
    #pragma unroll
    for (int t = 0; t < 32; t++) {
        s[t][0] = __expf(s[t][0] * 0.125f);
        s[t][1] = __expf(s[t][1] * 0.125f);
        s[t][2] = __expf(s[t][2] * 0.125f);
        s[t][3] = __expf(s[t][3] * 0.125f);
        const int c = t * 8 + tg * 2;
        float2 e1g = *(const float2*)(e1 + c);
        float2 e1h = *(const float2*)(e1 + 8 * NDIM + c);
        float2 e2g = *(const float2*)(e2 + c);
        float2 e2h = *(const float2*)(e2 + 8 * NDIM + c);
        d1a += s[t][0] * e1g.x + s[t][1] * e1g.y;
        d1b += s[t][2] * e1h.x + s[t][3] * e1h.y;
        d2a += s[t][0] * e2g.x + s[t][1] * e2g.y;
        d2b += s[t][2] * e2h.x + s[t][3] * e2h.y;
    }
    #pragma unroll
    for (int off = 1; off <= 2; off <<= 1) {
        d1a += __shfl_xor_sync(0xffffffffu, d1a, off);
        d1b += __shfl_xor_sync(0xffffffffu, d1b, off);
        d2a += __shfl_xor_sync(0xffffffffu, d2a, off);
        d2b += __shfl_xor_sync(0xffffffffu, d2b, off);
    }
    const float r1a = 1.f / d1a, r1b = 1.f / d1b;
    const float r2a = 1.f / d2a, r2b = 1.f / d2b;

    const int vrow_off = (lane & 7) + ((lane & 8) ? 8 : 0);
    const int vcol_off = (lane & 16) ? 8 : 0;

    // ---- pass A: O1 = softmax(S+b1) @ v_h (from kv) ----
    {
        float o1[8][4];
        #pragma unroll
        for (int nt = 0; nt < 8; nt++)
            #pragma unroll
            for (int q = 0; q < 4; q++) o1[nt][q] = 0.f;

        const __half* vsrc = g_kv + ((size_t)(b * NDIM)) * TWOC + CDIM + h * DDIM;
        #pragma unroll
        for (int chunk = 0; chunk < 4; chunk++) {
            __syncthreads();
            for (int idx = tid; idx < 512; idx += 256) {
                int r = idx >> 3, c = idx & 7;
                *(uint4*)(sm + SV + r * 144 + c * 16) =
                    *(const uint4*)(vsrc + (size_t)(chunk * 64 + r) * TWOC + c * 8);
            }
            __syncthreads();
            #pragma unroll
            for (int kk = 0; kk < 4; kk++) {
                const int t0 = chunk * 8 + kk * 2;
                const int ca = t0 * 8 + tg * 2;
                float2 eA = *(const float2*)(e1 + ca);
                float2 eB = *(const float2*)(e1 + 8 * NDIM + ca);
                float2 eC = *(const float2*)(e1 + ca + 8);
                float2 eD = *(const float2*)(e1 + 8 * NDIM + ca + 8);
                uint32_t pH[4];
                pH[0] = pack_h2(s[t0][0] * eA.x * r1a,     s[t0][1] * eA.y * r1a);
                pH[1] = pack_h2(s[t0][2] * eB.x * r1b,     s[t0][3] * eB.y * r1b);
                pH[2] = pack_h2(s[t0 + 1][0] * eC.x * r1a, s[t0 + 1][1] * eC.y * r1a);
                pH[3] = pack_h2(s[t0 + 1][2] * eD.x * r1b, s[t0 + 1][3] * eD.y * r1b);
                const int vrow = kk * 16 + vrow_off;
                #pragma unroll
                for (int dp = 0; dp < 2; dp++) {
                    uint32_t b0[4], b1[4];
                    ldsm_x4t(b0, sbase + SV + vrow * 144 + ((2 * dp) * 16 + vcol_off) * 2);
                    ldsm_x4t(b1, sbase + SV + vrow * 144 + ((2 * dp + 1) * 16 + vcol_off) * 2);
                    mma16816(o1[4 * dp + 0], pH, b0);
                    mma16816(o1[4 * dp + 1], pH, b0 + 2);
                    mma16816(o1[4 * dp + 2], pH, b1);
                    mma16816(o1[4 * dp + 3], pH, b1 + 2);
                }
            }
        }
        const size_t orow = (size_t)(b * NDIM + n0 + i0 + g);
        #pragma unroll
        for (int nt = 0; nt < 8; nt++) {
            const int col = h * DDIM + nt * 8 + tg * 2;
            *(__half2*)&g_o1[orow * CDIM + col]       = __floats2half2_rn(o1[nt][0], o1[nt][1]);
            *(__half2*)&g_o1[(orow + 8) * CDIM + col] = __floats2half2_rn(o1[nt][2], o1[nt][3]);
        }
    }

    // ---- pass B: O2 = softmax(S+b2) @ v (from qv) ----
    {
        float o2[8][4];
        #pragma unroll
        for (int nt = 0; nt < 8; nt++)
            #pragma unroll
            for (int q = 0; q < 4; q++) o2[nt][q] = 0.f;

        const __half* vsrc = g_qv + ((size_t)(b * NDIM)) * TWOC + CDIM + h * DDIM;
        #pragma unroll
        for (int chunk = 0; chunk < 4; chunk++) {
            __syncthreads();
            for (int idx = tid; idx < 512; idx += 256) {
                int r = idx >> 3, c = idx & 7;
                *(uint4*)(sm + SV + r * 144 + c * 16) =
                    *(const uint4*)(vsrc + (size_t)(chunk * 64 + r) * TWOC + c * 8);
            }
            __syncthreads();
            #pragma unroll
            for (int kk = 0; kk < 4; kk++) {
                const int t0 = chunk * 8 + kk * 2;
                const int ca = t0 * 8 + tg * 2;
                float2 eA = *(const float2*)(e2 + ca);
                float2 eB = *(const float2*)(e2 + 8 * NDIM + ca);
                float2 eC = *(const float2*)(e2 + ca + 8);
                float2 eD = *(const float2*)(e2 + 8 * NDIM + ca + 8);
                uint32_t pH[4];
                pH[0] = pack_h2(s[t0][0] * eA.x * r2a,     s[t0][1] * eA.y * r2a);
                pH[1] = pack_h2(s[t0][2] * eB.x * r2b,     s[t0][3] * eB.y * r2b);
                pH[2] = pack_h2(s[t0 + 1][0] * eC.x * r2a, s[t0 + 1][1] * eC.y * r2a);
                pH[3] = pack_h2(s[t0 + 1][2] * eD.x * r2b, s[t0 + 1][3] * eD.y * r2b);
                const int vrow = kk * 16 + vrow_off;
                #pragma unroll
                for (int dp = 0; dp < 2; dp++) {
                    uint32_t b0[4], b1[4];
                    ldsm_x4t(b0, sbase + SV + vrow * 144 + ((2 * dp) * 16 + vcol_off) * 2);
                    ldsm_x4t(b1, sbase + SV + vrow * 144 + ((2 * dp + 1) * 16 + vcol_off) * 2);
                    mma16816(o2[4 * dp + 0], pH, b0);
                    mma16816(o2[4 * dp + 1], pH, b0 + 2);
                    mma16816(o2[4 * dp + 2], pH, b1);
                    mma16816(o2[4 * dp + 3], pH, b1 + 2);
                }
            }
        }
        const size_t orow = (size_t)(b * NDIM + n0 + i0 + g);
        #pragma unroll
        for (int nt = 0; nt < 8; nt++) {
            const int col = h * DDIM + nt * 8 + tg * 2;
            *(__half2*)&g_o2[orow * CDIM + col]       = __floats2half2_rn(o2[nt][0], o2[nt][1]);
            *(__half2*)&g_o2[(orow + 8) * CDIM + col] = __floats2half2_rn(o2[nt][2], o2[nt][3]);
        }
    }
}

// ---------------- launch ----------------
extern "C" void kernel_launch(void* const* d_in, const int* in_sizes, int n_in,
                              void* d_out, int out_size)
{
    const float* x1    = (const float*)d_in[0];
    const float* x2    = (const float*)d_in[1];
    const float* qv_w  = (const float*)d_in[2];
    const float* qv_b  = (const float*)d_in[3];
    const float* kv_w  = (const float*)d_in[4];
    const float* kv_b  = (const float*)d_in[5];
    const float* p1w   = (const float*)d_in[6];
    const float* p1b   = (const float*)d_in[7];
    const float* p2w   = (const float*)d_in[8];
    const float* p2b   = (const float*)d_in[9];
    const float* rpb   = (const float*)d_in[10];
    const float* ppw   = (const float*)d_in[11];
    const float* ppb   = (const float*)d_in[12];
    const float* ln1g  = (const float*)d_in[13];
    const float* ln1b  = (const float*)d_in[14];
    const float* l1w   = (const float*)d_in[15];
    const float* l1b   = (const float*)d_in[16];
    const float* ln2g  = (const float*)d_in[17];
    const float* ln2b  = (const float*)d_in[18];
    const float* l2w   = (const float*)d_in[19];
    const float* l2b   = (const float*)d_in[20];
    const float* ln3g  = (const float*)d_in[21];
    const float* ln3b  = (const float*)d_in[22];
    const float* l3w   = (const float*)d_in[23];
    const float* l3b   = (const float*)d_in[24];
    const int*   rpi   = (const int*)d_in[25];
    float* out = (float*)d_out;

    __half *px, *pw, *pqv, *pkv, *po1, *po2;
    cudaGetSymbolAddress((void**)&px, g_x);
    cudaGetSymbolAddress((void**)&pw, g_w);
    cudaGetSymbolAddress((void**)&pqv, g_qv);
    cudaGetSymbolAddress((void**)&pkv, g_kv);
    cudaGetSymbolAddress((void**)&po1, g_o1);
    cudaGetSymbolAddress((void**)&po2, g_o2);

    cudaFuncSetAttribute(mma_gemm_kernel,
                         cudaFuncAttributeMaxDynamicSharedMemorySize, GEMM_SMEM);
    cudaFuncSetAttribute(attn_mma_kernel,
                         cudaFuncAttributeMaxDynamicSharedMemorySize, ATTN_SMEM);

    const int X4 = (int)(AELEM / 4);

    // 1) positional MLP + pre-exponentiated bias tables
    pos_mlp_kernel<<<4, 256>>>(ppw, ppb, ln1g, ln1b, l1w, l1b,
                               ln2g, ln2b, l2w, l2b, ln3g, ln3b, l3w, l3b);
    bias_build_kernel<<<(NHH * NDIM * NDIM) / 256, 256>>>(rpi, rpb);

    // 2) QV projection -> fp16
    conv_kernel<<<X4 / 256, 256>>>(x1, px, X4);
    wconvT_kernel<<<(TWOC * KDIM) / 256, 256>>>(qv_w, pw, TWOC);
    mma_gemm_kernel<<<dim3(TWOC / 128, MROWS / 128), 256, GEMM_SMEM>>>(
        px, pw, qv_b, nullptr, pqv, MROWS, TWOC, KDIM, 1);

    // 3) KV projection -> fp16
    conv_kernel<<<X4 / 256, 256>>>(x2, px, X4);
    wconvT_kernel<<<(TWOC * KDIM) / 256, 256>>>(kv_w, pw, TWOC);
    mma_gemm_kernel<<<dim3(TWOC / 128, MROWS / 128), 256, GEMM_SMEM>>>(
        px, pw, kv_b, nullptr, pkv, MROWS, TWOC, KDIM, 1);

    // 4) fp16 tensor-core dual-softmax attention
    attn_mma_kernel<<<dim3(NDIM / 128, NHH, BDIM), 256, ATTN_SMEM>>>();

    // 5) output projections into d_out (fp32)
    wconvT_kernel<<<(CDIM * KDIM) / 256, 256>>>(p1w, pw, CDIM);
    mma_gemm_kernel<<<dim3(CDIM / 128, MROWS / 128), 256, GEMM_SMEM>>>(
        po1, pw, p1b, out, nullptr, MROWS, CDIM, KDIM, 0);
    wconvT_kernel<<<(CDIM * KDIM) / 256, 256>>>(p2w, pw, CDIM);
    mma_gemm_kernel<<<dim3(CDIM / 128, MROWS / 128), 256, GEMM_SMEM>>>(
        po2, pw, p2b, out + AELEM, nullptr, MROWS, CDIM, KDIM, 0);
}

// round 15
// speedup vs baseline: 1.7402x; 1.0448x over previous
#include <cuda_runtime.h>
#include <cuda_fp16.h>
#include <cstdint>

// Problem constants
#define BDIM  128
#define NDIM  256
#define CDIM  384
#define NHH   6
#define DDIM  64
#define TWOC  768
#define NPOS  961
#define KDIM  384                    // GEMM K (== CDIM) for all projections
#define MROWS (BDIM * NDIM)          // 32768
#define AELEM ((size_t)MROWS * CDIM) // 12,582,912

// ---------------- device scratch ----------------
__device__ __half g_b1[(size_t)NHH * NDIM * NDIM];   // exp(bias1)[h][n][m], fp16
__device__ __half g_b2[(size_t)NHH * NDIM * NDIM];   // exp(bias2)[h][n][m], fp16
__device__ float  g_pos[NPOS * NHH];

// fp16 buffers (single precision products, fp32 accumulate)
__device__ __half g_x1[AELEM], g_x2[AELEM];
__device__ __half g_w1[CDIM * TWOC], g_w2[CDIM * TWOC];  // weights TRANSPOSED [Nc][K]
__device__ __half g_qv[(size_t)MROWS * TWOC];
__device__ __half g_kv[(size_t)MROWS * TWOC];
__device__ __half g_o1[AELEM], g_o2[AELEM];

// ---------------- low-level helpers ----------------
__device__ __forceinline__ void cpa16(uint32_t dst, const void* src) {
    asm volatile("cp.async.cg.shared.global [%0], [%1], 16;\n"
                 :: "r"(dst), "l"(src));
}
__device__ __forceinline__ void ldsm_x4(uint32_t* r, uint32_t a) {
    asm volatile("ldmatrix.sync.aligned.m8n8.x4.shared.b16 {%0,%1,%2,%3}, [%4];\n"
                 : "=r"(r[0]), "=r"(r[1]), "=r"(r[2]), "=r"(r[3]) : "r"(a));
}
__device__ __forceinline__ void ldsm_x4t(uint32_t* r, uint32_t a) {
    asm volatile("ldmatrix.sync.aligned.m8n8.x4.trans.shared.b16 {%0,%1,%2,%3}, [%4];\n"
                 : "=r"(r[0]), "=r"(r[1]), "=r"(r[2]), "=r"(r[3]) : "r"(a));
}
__device__ __forceinline__ void mma16816(float* c, const uint32_t* a,
                                         const uint32_t* b) {
    asm volatile(
        "mma.sync.aligned.m16n8k16.row.col.f32.f16.f16.f32 "
        "{%0,%1,%2,%3}, {%4,%5,%6,%7}, {%8,%9}, {%0,%1,%2,%3};\n"
        : "+f"(c[0]), "+f"(c[1]), "+f"(c[2]), "+f"(c[3])
        : "r"(a[0]), "r"(a[1]), "r"(a[2]), "r"(a[3]), "r"(b[0]), "r"(b[1]));
}
__device__ __forceinline__ uint32_t pack_h2(float a, float b) {
    __half2 h = __floats2half2_rn(a, b);   // .x = a (low half)
    return *reinterpret_cast<uint32_t*>(&h);
}

// ---------------- tiny positional MLP ----------------
__device__ __forceinline__ void ln_relu24(const float* x, const float* g,
                                          const float* b, float* y) {
    float m = 0.f;
    #pragma unroll
    for (int p = 0; p < 24; p++) m += x[p];
    m *= (1.f / 24.f);
    float v = 0.f;
    #pragma unroll
    for (int p = 0; p < 24; p++) { float d = x[p] - m; v += d * d; }
    v *= (1.f / 24.f);
    float rs = rsqrtf(v + 1e-5f);
    #pragma unroll
    for (int p = 0; p < 24; p++) {
        float val = (x[p] - m) * rs * g[p] + b[p];
        y[p] = fmaxf(val, 0.f);
    }
}

__global__ void pos_mlp_kernel(
    const float* __restrict__ ppw, const float* __restrict__ ppb,
    const float* __restrict__ g1, const float* __restrict__ b1,
    const float* __restrict__ w1, const float* __restrict__ wb1,
    const float* __restrict__ g2, const float* __restrict__ b2,
    const float* __restrict__ w2, const float* __restrict__ wb2,
    const float* __restrict__ g3, const float* __restrict__ b3,
    const float* __restrict__ w3, const float* __restrict__ wb3)
{
    int r = blockIdx.x * blockDim.x + threadIdx.x;
    if (r >= NPOS) return;
    float ph = (float)(r / 31 - 15);
    float pw = (float)(r % 31 - 15);
    float t[24], u[24], t2[24];
    #pragma unroll
    for (int p = 0; p < 24; p++) t[p] = ph * ppw[p] + pw * ppw[24 + p] + ppb[p];
    ln_relu24(t, g1, b1, u);
    for (int q = 0; q < 24; q++) {
        float a = wb1[q];
        for (int p = 0; p < 24; p++) a += u[p] * w1[p * 24 + q];
        t2[q] = a;
    }
    ln_relu24(t2, g2, b2, u);
    for (int q = 0; q < 24; q++) {
        float a = wb2[q];
        for (int p = 0; p < 24; p++) a += u[p] * w2[p * 24 + q];
        t[q] = a;
    }
    ln_relu24(t, g3, b3, u);
    for (int q = 0; q < NHH; q++) {
        float a = wb3[q];
        for (int p = 0; p < 24; p++) a += u[p] * w3[p * NHH + q];
        g_pos[r * NHH + q] = a;
    }
}

// ---------------- bias tables (pre-exponentiated, fp16) ----------------
__global__ void bias_build_kernel(const int* __restrict__ rpi,
                                  const float* __restrict__ rpb)
{
    int t = blockIdx.x * blockDim.x + threadIdx.x;
    int h  = t >> 16;
    int nm = t & 65535;
    int r = rpi[nm];
    g_b1[t] = __float2half(__expf(rpb[r * NHH + h]));
    g_b2[t] = __float2half(__expf(g_pos[r * NHH + h]));
}

// ---------------- fp32 -> fp16 convert (dual input via grid.y) ----------------
__global__ void conv2_kernel(const float* __restrict__ xa,
                             const float* __restrict__ xb,
                             __half* __restrict__ ya,
                             __half* __restrict__ yb, int n4)
{
    int i = blockIdx.x * blockDim.x + threadIdx.x;
    if (i >= n4) return;
    const float* x = blockIdx.y ? xb : xa;
    __half* y = blockIdx.y ? yb : ya;
    float4 v = ((const float4*)x)[i];
    ((__half2*)y)[2 * i]     = __floats2half2_rn(v.x, v.y);
    ((__half2*)y)[2 * i + 1] = __floats2half2_rn(v.z, v.w);
}

// ---------------- dual weight transpose-convert: W[K][Nc] -> Wt [Nc][K] ----------------
__global__ void wconvT2_kernel(const float* __restrict__ Wa,
                               const float* __restrict__ Wb,
                               __half* __restrict__ ya,
                               __half* __restrict__ yb, int Nc)
{
    int t = blockIdx.x * blockDim.x + threadIdx.x;   // t = n*K + k
    int n = t / KDIM, k = t - n * KDIM;
    const float* W = blockIdx.y ? Wb : Wa;
    __half* y = blockIdx.y ? yb : ya;
    y[t] = __float2half(W[(size_t)k * Nc + n]);
}

// ---------------- fp16 tensor-core GEMM (dual problem via grid.z) ----------------
// CTA tile 128x128, K-step 32, 8 warps (2x4), warp tile 64x32.
#define TILE_B 10240                     // bytes per tile (128 * 40 halves * 2)
#define STAGE_B (2 * TILE_B)             // 20480 bytes per stage
#define GEMM_SMEM (2 * STAGE_B)          // 40960 bytes

__global__ __launch_bounds__(256, 2) void mma_gemm_kernel(
    const __half* __restrict__ A0, const __half* __restrict__ A1,
    const __half* __restrict__ B0T, const __half* __restrict__ B1T,
    const float* __restrict__ bias0, const float* __restrict__ bias1,
    float* __restrict__ Cf0, float* __restrict__ Cf1,
    __half* __restrict__ Ch0, __half* __restrict__ Ch1,
    int Nc, int K, int halfOut)
{
    extern __shared__ __half sh[];
    const uint32_t sbase = (uint32_t)__cvta_generic_to_shared(sh);
    const int z = blockIdx.z;
    const __half* A  = z ? A1  : A0;
    const __half* BT = z ? B1T : B0T;
    const float* bias = z ? bias1 : bias0;
    float* Cf = z ? Cf1 : Cf0;
    __half* Ch = z ? Ch1 : Ch0;

    const int tid = threadIdx.x;
    const int lane = tid & 31;
    const int wid = tid >> 5;
    const int wm = wid >> 2;          // 0..1
    const int wn = wid & 3;           // 0..3
    const int rowBase = blockIdx.y * 128;
    const int colBase = blockIdx.x * 128;

    auto load_stage = [&](int s, int kt) {
        const int k0 = kt * 32;
        const uint32_t stg = sbase + s * STAGE_B;
        #pragma unroll
        for (int j = 0; j < 4; j++) {
            int idx = tid + j * 256;          // 0..1023
            int tile = idx >> 9;              // 0:A 1:BT
            int within = idx & 511;
            int row = within >> 2;            // 0..127
            int c8 = within & 3;              // 0..3 (8-half chunks)
            uint32_t dst = stg + tile * TILE_B + row * 80 + c8 * 16;
            const __half* src = (tile == 0)
                ? A  + (size_t)(rowBase + row) * K + k0 + c8 * 8
                : BT + (size_t)(colBase + row) * K + k0 + c8 * 8;
            cpa16(dst, src);
        }
        asm volatile("cp.async.commit_group;\n");
    };

    const int NK = K >> 5;   // 12
    load_stage(0, 0);
    load_stage(1, 1);
    asm volatile("cp.async.wait_group 1;\n");
    __syncthreads();

    float acc[4][4][4] = {};

    const int bro = ((lane >> 4) << 3) + (lane & 7);
    const int bco = ((lane >> 3) & 1) * 8;

    #pragma unroll 1
    for (int kt = 0; kt < NK; kt++) {
        const uint32_t stg = sbase + (kt & 1) * STAGE_B;
        #pragma unroll
        for (int k16 = 0; k16 < 2; k16++) {
            uint32_t bfr[2][4];
            #pragma unroll
            for (int np = 0; np < 2; np++) {
                uint32_t ba = stg + TILE_B +
                              (uint32_t)(wn * 32 + np * 16 + bro) * 80 +
                              (uint32_t)(k16 * 16 + bco) * 2;
                ldsm_x4(bfr[np], ba);
            }
            const int acol = k16 * 16 + ((lane >> 4) << 3);
            #pragma unroll
            for (int mt = 0; mt < 4; mt++) {
                const int arow = wm * 64 + mt * 16 + (lane & 15);
                uint32_t a[4];
                ldsm_x4(a, stg + (uint32_t)arow * 80 + (uint32_t)acol * 2);
                #pragma unroll
                for (int nt = 0; nt < 4; nt++)
                    mma16816(acc[mt][nt], a, &bfr[nt >> 1][(nt & 1) * 2]);
            }
        }
        __syncthreads();
        if (kt + 2 < NK) {
            load_stage(kt & 1, kt + 2);
            asm volatile("cp.async.wait_group 1;\n");
        } else {
            asm volatile("cp.async.wait_group 0;\n");
        }
        __syncthreads();
    }

    const int g = lane >> 2, tg = lane & 3;
    #pragma unroll
    for (int mt = 0; mt < 4; mt++) {
        const int r0 = rowBase + wm * 64 + mt * 16 + g;
        #pragma unroll
        for (int nt = 0; nt < 4; nt++) {
            const int c0 = colBase + wn * 32 + nt * 8 + tg * 2;
            const float b0 = bias[c0], b1 = bias[c0 + 1];
            float v0 = acc[mt][nt][0] + b0, v1 = acc[mt][nt][1] + b1;
            float v2 = acc[mt][nt][2] + b0, v3 = acc[mt][nt][3] + b1;
            if (halfOut) {
                *(__half2*)&Ch[(size_t)r0 * Nc + c0]       = __floats2half2_rn(v0, v1);
                *(__half2*)&Ch[(size_t)(r0 + 8) * Nc + c0] = __floats2half2_rn(v2, v3);
            } else {
                float2 lo = { v0, v1 };
                float2 hi = { v2, v3 };
                *(float2*)&Cf[(size_t)r0 * Nc + c0]       = lo;
                *(float2*)&Cf[(size_t)(r0 + 8) * Nc + c0] = hi;
            }
        }
    }
}

// ---------------- fp16 tensor-core dual-softmax attention ----------------
#define SQ 0
#define SK 18432
#define SV 18432
#define ATTN_SMEM 55296

__global__ __launch_bounds__(256, 1) void attn_mma_kernel()
{
    extern __shared__ char sm[];
    const uint32_t sbase = (uint32_t)__cvta_generic_to_shared(sm);
    const int b = blockIdx.z, h = blockIdx.y, n0 = blockIdx.x * 128;
    const int tid = threadIdx.x;
    const int lane = tid & 31;
    const int wid = tid >> 5;
    const int g = lane >> 2, tg = lane & 3;
    const int i0 = wid * 16;

    {
        const __half* q = g_qv + ((size_t)(b * NDIM + n0)) * TWOC + h * DDIM;
        for (int idx = tid; idx < 1024; idx += 256) {
            int r = idx >> 3, c = idx & 7;
            *(uint4*)(sm + SQ + r * 144 + c * 16) = *(const uint4*)(q + (size_t)r * TWOC + c * 8);
        }
        const __half* k = g_kv + ((size_t)(b * NDIM)) * TWOC + h * DDIM;
        for (int idx = tid; idx < 2048; idx += 256) {
            int r = idx >> 3, c = idx & 7;
            *(uint4*)(sm + SK + r * 144 + c * 16) = *(const uint4*)(k + (size_t)r * TWOC + c * 8);
        }
    }
    __syncthreads();

    float s[32][4];
    #pragma unroll
    for (int t = 0; t < 32; t++)
        #pragma unroll
        for (int q = 0; q < 4; q++) s[t][q] = 0.f;

    const int arow = i0 + (lane & 15);
    const int krow_off = (lane & 7) + ((lane & 16) ? 8 : 0);
    #pragma unroll
    for (int d0 = 0; d0 < 64; d0 += 16) {
        uint32_t a[4];
        const int acol = d0 + ((lane & 16) ? 8 : 0);
        ldsm_x4(a, sbase + SQ + arow * 144 + acol * 2);
        const int kcol = d0 + ((lane & 8) ? 8 : 0);
        #pragma unroll
        for (int jp = 0; jp < 8; jp++) {
            uint32_t b0[4], b1[4];
            ldsm_x4(b0, sbase + SK + ((2 * jp) * 16 + krow_off) * 144 + kcol * 2);
            ldsm_x4(b1, sbase + SK + ((2 * jp + 1) * 16 + krow_off) * 144 + kcol * 2);
            mma16816(s[4 * jp + 0], a, b0);
            mma16816(s[4 * jp + 1], a, b0 + 2);
            mma16816(s[4 * jp + 2], a, b1);
            mma16816(s[4 * jp + 3], a, b1 + 2);
        }
    }

    const int rowg = n0 + i0 + g;
    const __half* e1 = g_b1 + ((size_t)h * NDIM + rowg) * NDIM;
    const __half* e2 = g_b2 + ((size_t)h * NDIM + rowg) * NDIM;
    float d1a = 0.f, d1b = 0.f, d2a = 0.f, d2b = 0.f;
    #pragma unroll
    for (int t = 0; t < 32; t++) {
        s[t][0] = __expf(s[t][0] * 0.125f);
        s[t][1] = __expf(s[t][1] * 0.125f);
        s[t][2] = __expf(s[t][2] * 0.125f);
        s[t][3] = __expf(s[t][3] * 0.125f);
        const int c = t * 8 + tg * 2;
        float2 e1g = __half22float2(*(const __half2*)(e1 + c));
        float2 e1h = __half22float2(*(const __half2*)(e1 + 8 * NDIM + c));
        float2 e2g = __half22float2(*(const __half2*)(e2 + c));
        float2 e2h = __half22float2(*(const __half2*)(e2 + 8 * NDIM + c));
        d1a += s[t][0] * e1g.x + s[t][1] * e1g.y;
        d1b += s[t][2] * e1h.x + s[t][3] * e1h.y;
        d2a += s[t][0] * e2g.x + s[t][1] * e2g.y;
        d2b += s[t][2] * e2h.x + s[t][3] * e2h.y;
    }
    #pragma unroll
    for (int off = 1; off <= 2; off <<= 1) {
        d1a += __shfl_xor_sync(0xffffffffu, d1a, off);
        d1b += __shfl_xor_sync(0xffffffffu, d1b, off);
        d2a += __shfl_xor_sync(0xffffffffu, d2a, off);
        d2b += __shfl_xor_sync(0xffffffffu, d2b, off);
    }
    const float r1a = 1.f / d1a, r1b = 1.f / d1b;
    const float r2a = 1.f / d2a, r2b = 1.f / d2b;

    const int vrow_off = (lane & 7) + ((lane & 8) ? 8 : 0);
    const int vcol_off = (lane & 16) ? 8 : 0;

    // ---- pass A: O1 = softmax(S+b1) @ v_h (from kv) ----
    {
        float o1[8][4];
        #pragma unroll
        for (int nt = 0; nt < 8; nt++)
            #pragma unroll
            for (int q = 0; q < 4; q++) o1[nt][q] = 0.f;

        const __half* vsrc = g_kv + ((size_t)(b * NDIM)) * TWOC + CDIM + h * DDIM;
        #pragma unroll
        for (int chunk = 0; chunk < 4; chunk++) {
            __syncthreads();
            for (int idx = tid; idx < 512; idx += 256) {
                int r = idx >> 3, c = idx & 7;
                *(uint4*)(sm + SV + r * 144 + c * 16) =
                    *(const uint4*)(vsrc + (size_t)(chunk * 64 + r) * TWOC + c * 8);
            }
            __syncthreads();
            #pragma unroll
            for (int kk = 0; kk < 4; kk++) {
                const int t0 = chunk * 8 + kk * 2;
                const int ca = t0 * 8 + tg * 2;
                float2 eA = __half22float2(*(const __half2*)(e1 + ca));
                float2 eB = __half22float2(*(const __half2*)(e1 + 8 * NDIM + ca));
                float2 eC = __half22float2(*(const __half2*)(e1 + ca + 8));
                float2 eD = __half22float2(*(const __half2*)(e1 + 8 * NDIM + ca + 8));
                uint32_t pH[4];
                pH[0] = pack_h2(s[t0][0] * eA.x * r1a,     s[t0][1] * eA.y * r1a);
                pH[1] = pack_h2(s[t0][2] * eB.x * r1b,     s[t0][3] * eB.y * r1b);
                pH[2] = pack_h2(s[t0 + 1][0] * eC.x * r1a, s[t0 + 1][1] * eC.y * r1a);
                pH[3] = pack_h2(s[t0 + 1][2] * eD.x * r1b, s[t0 + 1][3] * eD.y * r1b);
                const int vrow = kk * 16 + vrow_off;
                #pragma unroll
                for (int dp = 0; dp < 2; dp++) {
                    uint32_t b0[4], b1[4];
                    ldsm_x4t(b0, sbase + SV + vrow * 144 + ((2 * dp) * 16 + vcol_off) * 2);
                    ldsm_x4t(b1, sbase + SV + vrow * 144 + ((2 * dp + 1) * 16 + vcol_off) * 2);
                    mma16816(o1[4 * dp + 0], pH, b0);
                    mma16816(o1[4 * dp + 1], pH, b0 + 2);
                    mma16816(o1[4 * dp + 2], pH, b1);
                    mma16816(o1[4 * dp + 3], pH, b1 + 2);
                }
            }
        }
        const size_t orow = (size_t)(b * NDIM + n0 + i0 + g);
        #pragma unroll
        for (int nt = 0; nt < 8; nt++) {
            const int col = h * DDIM + nt * 8 + tg * 2;
            *(__half2*)&g_o1[orow * CDIM + col]       = __floats2half2_rn(o1[nt][0], o1[nt][1]);
            *(__half2*)&g_o1[(orow + 8) * CDIM + col] = __floats2half2_rn(o1[nt][2], o1[nt][3]);
        }
    }

    // ---- pass B: O2 = softmax(S+b2) @ v (from qv) ----
    {
        float o2[8][4];
        #pragma unroll
        for (int nt = 0; nt < 8; nt++)
            #pragma unroll
            for (int q = 0; q < 4; q++) o2[nt][q] = 0.f;

        const __half* vsrc = g_qv + ((size_t)(b * NDIM)) * TWOC + CDIM + h * DDIM;
        #pragma unroll
        for (int chunk = 0; chunk < 4; chunk++) {
            __syncthreads();
            for (int idx = tid; idx < 512; idx += 256) {
                int r = idx >> 3, c = idx & 7;
                *(uint4*)(sm + SV + r * 144 + c * 16) =
                    *(const uint4*)(vsrc + (size_t)(chunk * 64 + r) * TWOC + c * 8);
            }
            __syncthreads();
            #pragma unroll
            for (int kk = 0; kk < 4; kk++) {
                const int t0 = chunk * 8 + kk * 2;
                const int ca = t0 * 8 + tg * 2;
                float2 eA = __half22float2(*(const __half2*)(e2 + ca));
                float2 eB = __half22float2(*(const __half2*)(e2 + 8 * NDIM + ca));
                float2 eC = __half22float2(*(const __half2*)(e2 + ca + 8));
                float2 eD = __half22float2(*(const __half2*)(e2 + 8 * NDIM + ca + 8));
                uint32_t pH[4];
                pH[0] = pack_h2(s[t0][0] * eA.x * r2a,     s[t0][1] * eA.y * r2a);
                pH[1] = pack_h2(s[t0][2] * eB.x * r2b,     s[t0][3] * eB.y * r2b);
                pH[2] = pack_h2(s[t0 + 1][0] * eC.x * r2a, s[t0 + 1][1] * eC.y * r2a);
                pH[3] = pack_h2(s[t0 + 1][2] * eD.x * r2b, s[t0 + 1][3] * eD.y * r2b);
                const int vrow = kk * 16 + vrow_off;
                #pragma unroll
                for (int dp = 0; dp < 2; dp++) {
                    uint32_t b0[4], b1[4];
                    ldsm_x4t(b0, sbase + SV + vrow * 144 + ((2 * dp) * 16 + vcol_off) * 2);
                    ldsm_x4t(b1, sbase + SV + vrow * 144 + ((2 * dp + 1) * 16 + vcol_off) * 2);
                    mma16816(o2[4 * dp + 0], pH, b0);
                    mma16816(o2[4 * dp + 1], pH, b0 + 2);
                    mma16816(o2[4 * dp + 2], pH, b1);
                    mma16816(o2[4 * dp + 3], pH, b1 + 2);
                }
            }
        }
        const size_t orow = (size_t)(b * NDIM + n0 + i0 + g);
        #pragma unroll
        for (int nt = 0; nt < 8; nt++) {
            const int col = h * DDIM + nt * 8 + tg * 2;
            *(__half2*)&g_o2[orow * CDIM + col]       = __floats2half2_rn(o2[nt][0], o2[nt][1]);
            *(__half2*)&g_o2[(orow + 8) * CDIM + col] = __floats2half2_rn(o2[nt][2], o2[nt][3]);
        }
    }
}

// ---------------- launch ----------------
extern "C" void kernel_launch(void* const* d_in, const int* in_sizes, int n_in,
                              void* d_out, int out_size)
{
    const float* x1    = (const float*)d_in[0];
    const float* x2    = (const float*)d_in[1];
    const float* qv_w  = (const float*)d_in[2];
    const float* qv_b  = (const float*)d_in[3];
    const float* kv_w  = (const float*)d_in[4];
    const float* kv_b  = (const float*)d_in[5];
    const float* p1w   = (const float*)d_in[6];
    const float* p1b   = (const float*)d_in[7];
    const float* p2w   = (const float*)d_in[8];
    const float* p2b   = (const float*)d_in[9];
    const float* rpb   = (const float*)d_in[10];
    const float* ppw   = (const float*)d_in[11];
    const float* ppb   = (const float*)d_in[12];
    const float* ln1g  = (const float*)d_in[13];
    const float* ln1b  = (const float*)d_in[14];
    const float* l1w   = (const float*)d_in[15];
    const float* l1b   = (const float*)d_in[16];
    const float* ln2g  = (const float*)d_in[17];
    const float* ln2b  = (const float*)d_in[18];
    const float* l2w   = (const float*)d_in[19];
    const float* l2b   = (const float*)d_in[20];
    const float* ln3g  = (const float*)d_in[21];
    const float* ln3b  = (const float*)d_in[22];
    const float* l3w   = (const float*)d_in[23];
    const float* l3b   = (const float*)d_in[24];
    const int*   rpi   = (const int*)d_in[25];
    float* out = (float*)d_out;

    __half *px1, *px2, *pw1, *pw2, *pqv, *pkv, *po1, *po2;
    cudaGetSymbolAddress((void**)&px1, g_x1);
    cudaGetSymbolAddress((void**)&px2, g_x2);
    cudaGetSymbolAddress((void**)&pw1, g_w1);
    cudaGetSymbolAddress((void**)&pw2, g_w2);
    cudaGetSymbolAddress((void**)&pqv, g_qv);
    cudaGetSymbolAddress((void**)&pkv, g_kv);
    cudaGetSymbolAddress((void**)&po1, g_o1);
    cudaGetSymbolAddress((void**)&po2, g_o2);

    cudaFuncSetAttribute(mma_gemm_kernel,
                         cudaFuncAttributeMaxDynamicSharedMemorySize, GEMM_SMEM);
    cudaFuncSetAttribute(attn_mma_kernel,
                         cudaFuncAttributeMaxDynamicSharedMemorySize, ATTN_SMEM);

    const int X4 = (int)(AELEM / 4);

    // 1) positional MLP + pre-exponentiated fp16 bias tables
    pos_mlp_kernel<<<4, 256>>>(ppw, ppb, ln1g, ln1b, l1w, l1b,
                               ln2g, ln2b, l2w, l2b, ln3g, ln3b, l3w, l3b);
    bias_build_kernel<<<(NHH * NDIM * NDIM) / 256, 256>>>(rpi, rpb);

    // 2) converts (both inputs, both QV/KV weights)
    conv2_kernel<<<dim3(X4 / 256, 2), 256>>>(x1, x2, px1, px2, X4);
    wconvT2_kernel<<<dim3((TWOC * KDIM) / 256, 2), 256>>>(qv_w, kv_w, pw1, pw2, TWOC);

    // 3) fused QV+KV projections (grid.z selects problem)
    mma_gemm_kernel<<<dim3(TWOC / 128, MROWS / 128, 2), 256, GEMM_SMEM>>>(
        px1, px2, pw1, pw2, qv_b, kv_b, nullptr, nullptr, pqv, pkv, TWOC, KDIM, 1);

    // 4) fp16 tensor-core dual-softmax attention
    attn_mma_kernel<<<dim3(NDIM / 128, NHH, BDIM), 256, ATTN_SMEM>>>();

    // 5) fused output projections into d_out (fp32)
    wconvT2_kernel<<<dim3((CDIM * KDIM) / 256, 2), 256>>>(p1w, p2w, pw1, pw2, CDIM);
    mma_gemm_kernel<<<dim3(CDIM / 128, MROWS / 128, 2), 256, GEMM_SMEM>>>(
        po1, po2, pw1, pw2, p1b, p2b, out, out + AELEM, nullptr, nullptr, CDIM, KDIM, 0);
}

// round 16
// speedup vs baseline: 2.0750x; 1.1924x over previous
#include <cuda_runtime.h>
#include <cuda_fp16.h>
#include <cstdint>

// Problem constants
#define BDIM  128
#define NDIM  256
#define CDIM  384
#define NHH   6
#define DDIM  64
#define TWOC  768
#define NPOS  961
#define KDIM  384                    // GEMM K (== CDIM) for all projections
#define NKSTEPS 12                   // KDIM / 32, compile-time
#define MROWS (BDIM * NDIM)          // 32768
#define AELEM ((size_t)MROWS * CDIM) // 12,582,912

// ---------------- device scratch ----------------
__device__ __half g_b1[(size_t)NHH * NDIM * NDIM];   // exp(bias1)[h][n][m], fp16
__device__ __half g_b2[(size_t)NHH * NDIM * NDIM];   // exp(bias2)[h][n][m], fp16
__device__ float  g_pos[NPOS * NHH];

// fp16 buffers (single precision products, fp32 accumulate)
__device__ __half g_x1[AELEM], g_x2[AELEM];
__device__ __half g_w1[CDIM * TWOC], g_w2[CDIM * TWOC];  // weights TRANSPOSED [Nc][K]
__device__ __half g_qv[(size_t)MROWS * TWOC];
__device__ __half g_kv[(size_t)MROWS * TWOC];
__device__ __half g_o1[AELEM], g_o2[AELEM];

// ---------------- low-level helpers ----------------
__device__ __forceinline__ void cpa16(uint32_t dst, const void* src) {
    asm volatile("cp.async.cg.shared.global [%0], [%1], 16;\n"
                 :: "r"(dst), "l"(src));
}
#define CP_COMMIT() asm volatile("cp.async.commit_group;\n")
#define CP_WAIT(n)  asm volatile("cp.async.wait_group %0;\n" :: "n"(n))

__device__ __forceinline__ void ldsm_x4(uint32_t* r, uint32_t a) {
    asm volatile("ldmatrix.sync.aligned.m8n8.x4.shared.b16 {%0,%1,%2,%3}, [%4];\n"
                 : "=r"(r[0]), "=r"(r[1]), "=r"(r[2]), "=r"(r[3]) : "r"(a));
}
__device__ __forceinline__ void ldsm_x4t(uint32_t* r, uint32_t a) {
    asm volatile("ldmatrix.sync.aligned.m8n8.x4.trans.shared.b16 {%0,%1,%2,%3}, [%4];\n"
                 : "=r"(r[0]), "=r"(r[1]), "=r"(r[2]), "=r"(r[3]) : "r"(a));
}
__device__ __forceinline__ void mma16816(float* c, const uint32_t* a,
                                         const uint32_t* b) {
    asm volatile(
        "mma.sync.aligned.m16n8k16.row.col.f32.f16.f16.f32 "
        "{%0,%1,%2,%3}, {%4,%5,%6,%7}, {%8,%9}, {%0,%1,%2,%3};\n"
        : "+f"(c[0]), "+f"(c[1]), "+f"(c[2]), "+f"(c[3])
        : "r"(a[0]), "r"(a[1]), "r"(a[2]), "r"(a[3]), "r"(b[0]), "r"(b[1]));
}
__device__ __forceinline__ uint32_t pack_h2(float a, float b) {
    __half2 h = __floats2half2_rn(a, b);   // .x = a (low half)
    return *reinterpret_cast<uint32_t*>(&h);
}

// ---------------- tiny positional MLP ----------------
__device__ __forceinline__ void ln_relu24(const float* x, const float* g,
                                          const float* b, float* y) {
    float m = 0.f;
    #pragma unroll
    for (int p = 0; p < 24; p++) m += x[p];
    m *= (1.f / 24.f);
    float v = 0.f;
    #pragma unroll
    for (int p = 0; p < 24; p++) { float d = x[p] - m; v += d * d; }
    v *= (1.f / 24.f);
    float rs = rsqrtf(v + 1e-5f);
    #pragma unroll
    for (int p = 0; p < 24; p++) {
        float val = (x[p] - m) * rs * g[p] + b[p];
        y[p] = fmaxf(val, 0.f);
    }
}

__global__ void pos_mlp_kernel(
    const float* __restrict__ ppw, const float* __restrict__ ppb,
    const float* __restrict__ g1, const float* __restrict__ b1,
    const float* __restrict__ w1, const float* __restrict__ wb1,
    const float* __restrict__ g2, const float* __restrict__ b2,
    const float* __restrict__ w2, const float* __restrict__ wb2,
    const float* __restrict__ g3, const float* __restrict__ b3,
    const float* __restrict__ w3, const float* __restrict__ wb3)
{
    int r = blockIdx.x * blockDim.x + threadIdx.x;
    if (r >= NPOS) return;
    float ph = (float)(r / 31 - 15);
    float pw = (float)(r % 31 - 15);
    float t[24], u[24], t2[24];
    #pragma unroll
    for (int p = 0; p < 24; p++) t[p] = ph * ppw[p] + pw * ppw[24 + p] + ppb[p];
    ln_relu24(t, g1, b1, u);
    for (int q = 0; q < 24; q++) {
        float a = wb1[q];
        for (int p = 0; p < 24; p++) a += u[p] * w1[p * 24 + q];
        t2[q] = a;
    }
    ln_relu24(t2, g2, b2, u);
    for (int q = 0; q < 24; q++) {
        float a = wb2[q];
        for (int p = 0; p < 24; p++) a += u[p] * w2[p * 24 + q];
        t[q] = a;
    }
    ln_relu24(t, g3, b3, u);
    for (int q = 0; q < NHH; q++) {
        float a = wb3[q];
        for (int p = 0; p < 24; p++) a += u[p] * w3[p * NHH + q];
        g_pos[r * NHH + q] = a;
    }
}

// ---------------- bias tables (pre-exponentiated, fp16) ----------------
__global__ void bias_build_kernel(const int* __restrict__ rpi,
                                  const float* __restrict__ rpb)
{
    int t = blockIdx.x * blockDim.x + threadIdx.x;
    int h  = t >> 16;
    int nm = t & 65535;
    int r = rpi[nm];
    g_b1[t] = __float2half(__expf(rpb[r * NHH + h]));
    g_b2[t] = __float2half(__expf(g_pos[r * NHH + h]));
}

// ---------------- fp32 -> fp16 convert (dual input via grid.y) ----------------
__global__ void conv2_kernel(const float* __restrict__ xa,
                             const float* __restrict__ xb,
                             __half* __restrict__ ya,
                             __half* __restrict__ yb, int n4)
{
    int i = blockIdx.x * blockDim.x + threadIdx.x;
    if (i >= n4) return;
    const float* x = blockIdx.y ? xb : xa;
    __half* y = blockIdx.y ? yb : ya;
    float4 v = ((const float4*)x)[i];
    ((__half2*)y)[2 * i]     = __floats2half2_rn(v.x, v.y);
    ((__half2*)y)[2 * i + 1] = __floats2half2_rn(v.z, v.w);
}

// ---------------- dual weight transpose-convert: W[K][Nc] -> Wt [Nc][K] ----------------
__global__ void wconvT2_kernel(const float* __restrict__ Wa,
                               const float* __restrict__ Wb,
                               __half* __restrict__ ya,
                               __half* __restrict__ yb, int Nc)
{
    int t = blockIdx.x * blockDim.x + threadIdx.x;   // t = n*K + k
    int n = t / KDIM, k = t - n * KDIM;
    const float* W = blockIdx.y ? Wb : Wa;
    __half* y = blockIdx.y ? yb : ya;
    y[t] = __float2half(W[(size_t)k * Nc + n]);
}

// ---------------- fp16 tensor-core GEMM (dual problem via grid.z, 3-stage) ----------------
#define TILE_B 10240                     // bytes per tile (128 * 40 halves * 2)
#define STAGE_B (2 * TILE_B)             // 20480 bytes per stage
#define GEMM_SMEM (3 * STAGE_B)          // 61440 bytes (3 stages)

__global__ __launch_bounds__(256, 2) void mma_gemm_kernel(
    const __half* __restrict__ A0, const __half* __restrict__ A1,
    const __half* __restrict__ B0T, const __half* __restrict__ B1T,
    const float* __restrict__ bias0, const float* __restrict__ bias1,
    float* __restrict__ Cf0, float* __restrict__ Cf1,
    __half* __restrict__ Ch0, __half* __restrict__ Ch1,
    int Nc, int halfOut)
{
    extern __shared__ __half sh[];
    const uint32_t sbase = (uint32_t)__cvta_generic_to_shared(sh);
    const int z = blockIdx.z;
    const __half* A  = z ? A1  : A0;
    const __half* BT = z ? B1T : B0T;
    const float* bias = z ? bias1 : bias0;
    float* Cf = z ? Cf1 : Cf0;
    __half* Ch = z ? Ch1 : Ch0;

    const int tid = threadIdx.x;
    const int lane = tid & 31;
    const int wid = tid >> 5;
    const int wm = wid >> 2;          // 0..1
    const int wn = wid & 3;           // 0..3
    const int rowBase = blockIdx.y * 128;
    const int colBase = blockIdx.x * 128;

    auto load_stage = [&](int s, int kt) {
        const int k0 = kt * 32;
        const uint32_t stg = sbase + s * STAGE_B;
        #pragma unroll
        for (int j = 0; j < 4; j++) {
            int idx = tid + j * 256;          // 0..1023
            int tile = idx >> 9;              // 0:A 1:BT
            int within = idx & 511;
            int row = within >> 2;            // 0..127
            int c8 = within & 3;              // 0..3 (8-half chunks)
            uint32_t dst = stg + tile * TILE_B + row * 80 + c8 * 16;
            const __half* src = (tile == 0)
                ? A  + (size_t)(rowBase + row) * KDIM + k0 + c8 * 8
                : BT + (size_t)(colBase + row) * KDIM + k0 + c8 * 8;
            cpa16(dst, src);
        }
        CP_COMMIT();
    };

    load_stage(0, 0);
    load_stage(1, 1);
    load_stage(2, 2);

    float acc[4][4][4] = {};

    const int bro = ((lane >> 4) << 3) + (lane & 7);
    const int bco = ((lane >> 3) & 1) * 8;

    int s = 0;
    #pragma unroll 1
    for (int kt = 0; kt < NKSTEPS; kt++) {
        if (kt + 2 < NKSTEPS)      CP_WAIT(2);
        else if (kt + 1 < NKSTEPS) CP_WAIT(1);
        else                       CP_WAIT(0);
        __syncthreads();
        const uint32_t stg = sbase + s * STAGE_B;
        #pragma unroll
        for (int k16 = 0; k16 < 2; k16++) {
            uint32_t bfr[2][4];
            #pragma unroll
            for (int np = 0; np < 2; np++) {
                uint32_t ba = stg + TILE_B +
                              (uint32_t)(wn * 32 + np * 16 + bro) * 80 +
                              (uint32_t)(k16 * 16 + bco) * 2;
                ldsm_x4(bfr[np], ba);
            }
            const int acol = k16 * 16 + ((lane >> 4) << 3);
            #pragma unroll
            for (int mt = 0; mt < 4; mt++) {
                const int arow = wm * 64 + mt * 16 + (lane & 15);
                uint32_t a[4];
                ldsm_x4(a, stg + (uint32_t)arow * 80 + (uint32_t)acol * 2);
                #pragma unroll
                for (int nt = 0; nt < 4; nt++)
                    mma16816(acc[mt][nt], a, &bfr[nt >> 1][(nt & 1) * 2]);
            }
        }
        __syncthreads();
        if (kt + 3 < NKSTEPS) load_stage(s, kt + 3);
        s = (s == 2) ? 0 : s + 1;
    }

    const int g = lane >> 2, tg = lane & 3;
    #pragma unroll
    for (int mt = 0; mt < 4; mt++) {
        const int r0 = rowBase + wm * 64 + mt * 16 + g;
        #pragma unroll
        for (int nt = 0; nt < 4; nt++) {
            const int c0 = colBase + wn * 32 + nt * 8 + tg * 2;
            const float b0 = bias[c0], b1 = bias[c0 + 1];
            float v0 = acc[mt][nt][0] + b0, v1 = acc[mt][nt][1] + b1;
            float v2 = acc[mt][nt][2] + b0, v3 = acc[mt][nt][3] + b1;
            if (halfOut) {
                *(__half2*)&Ch[(size_t)r0 * Nc + c0]       = __floats2half2_rn(v0, v1);
                *(__half2*)&Ch[(size_t)(r0 + 8) * Nc + c0] = __floats2half2_rn(v2, v3);
            } else {
                float2 lo = { v0, v1 };
                float2 hi = { v2, v3 };
                *(float2*)&Cf[(size_t)r0 * Nc + c0]       = lo;
                *(float2*)&Cf[(size_t)(r0 + 8) * Nc + c0] = hi;
            }
        }
    }
}

// ---------------- fp16 tensor-core dual-softmax attention ----------------
// smem: Q 128x64 (stride 144B) at 0; K 256x64 at 18432; V double buffers:
// V1 overlays K rows 0-63 (dead after S phase), V0 is fresh space at 55296.
#define SQ 0
#define SK 18432
#define SV1 18432
#define SV0 55296
#define ATTN_SMEM 64512

__global__ __launch_bounds__(256, 1) void attn_mma_kernel()
{
    extern __shared__ char sm[];
    const uint32_t sbase = (uint32_t)__cvta_generic_to_shared(sm);
    const int b = blockIdx.z, h = blockIdx.y, n0 = blockIdx.x * 128;
    const int tid = threadIdx.x;
    const int lane = tid & 31;
    const int wid = tid >> 5;
    const int g = lane >> 2, tg = lane & 3;
    const int i0 = wid * 16;

    const __half* vA = g_kv + ((size_t)(b * NDIM)) * TWOC + CDIM + h * DDIM; // v_h
    const __half* vB = g_qv + ((size_t)(b * NDIM)) * TWOC + CDIM + h * DDIM; // v

    auto prefetchV = [&](const __half* vsrc, int chunk, uint32_t dst) {
        #pragma unroll
        for (int rep = 0; rep < 2; rep++) {
            int idx = tid + rep * 256;        // 0..511
            int r = idx >> 3, c = idx & 7;
            cpa16(dst + (uint32_t)(r * 144 + c * 16),
                  vsrc + (size_t)(chunk * 64 + r) * TWOC + c * 8);
        }
        CP_COMMIT();
    };

    // G0: pass-A chunk 0 into V0 (region disjoint from Q/K)
    prefetchV(vA, 0, sbase + SV0);

    {
        const __half* q = g_qv + ((size_t)(b * NDIM + n0)) * TWOC + h * DDIM;
        for (int idx = tid; idx < 1024; idx += 256) {
            int r = idx >> 3, c = idx & 7;
            *(uint4*)(sm + SQ + r * 144 + c * 16) = *(const uint4*)(q + (size_t)r * TWOC + c * 8);
        }
        const __half* k = g_kv + ((size_t)(b * NDIM)) * TWOC + h * DDIM;
        for (int idx = tid; idx < 2048; idx += 256) {
            int r = idx >> 3, c = idx & 7;
            *(uint4*)(sm + SK + r * 144 + c * 16) = *(const uint4*)(k + (size_t)r * TWOC + c * 8);
        }
    }
    __syncthreads();

    float s[32][4];
    #pragma unroll
    for (int t = 0; t < 32; t++)
        #pragma unroll
        for (int q = 0; q < 4; q++) s[t][q] = 0.f;

    const int arow = i0 + (lane & 15);
    const int krow_off = (lane & 7) + ((lane & 16) ? 8 : 0);
    #pragma unroll
    for (int d0 = 0; d0 < 64; d0 += 16) {
        uint32_t a[4];
        const int acol = d0 + ((lane & 16) ? 8 : 0);
        ldsm_x4(a, sbase + SQ + arow * 144 + acol * 2);
        const int kcol = d0 + ((lane & 8) ? 8 : 0);
        #pragma unroll
        for (int jp = 0; jp < 8; jp++) {
            uint32_t b0[4], b1[4];
            ldsm_x4(b0, sbase + SK + ((2 * jp) * 16 + krow_off) * 144 + kcol * 2);
            ldsm_x4(b1, sbase + SK + ((2 * jp + 1) * 16 + krow_off) * 144 + kcol * 2);
            mma16816(s[4 * jp + 0], a, b0);
            mma16816(s[4 * jp + 1], a, b0 + 2);
            mma16816(s[4 * jp + 2], a, b1);
            mma16816(s[4 * jp + 3], a, b1 + 2);
        }
    }

    const int rowg = n0 + i0 + g;
    const __half* e1 = g_b1 + ((size_t)h * NDIM + rowg) * NDIM;
    const __half* e2 = g_b2 + ((size_t)h * NDIM + rowg) * NDIM;
    float d1a = 0.f, d1b = 0.f, d2a = 0.f, d2b = 0.f;
    #pragma unroll
    for (int t = 0; t < 32; t++) {
        s[t][0] = __expf(s[t][0] * 0.125f);
        s[t][1] = __expf(s[t][1] * 0.125f);
        s[t][2] = __expf(s[t][2] * 0.125f);
        s[t][3] = __expf(s[t][3] * 0.125f);
        const int c = t * 8 + tg * 2;
        float2 e1g = __half22float2(*(const __half2*)(e1 + c));
        float2 e1h = __half22float2(*(const __half2*)(e1 + 8 * NDIM + c));
        float2 e2g = __half22float2(*(const __half2*)(e2 + c));
        float2 e2h = __half22float2(*(const __half2*)(e2 + 8 * NDIM + c));
        d1a += s[t][0] * e1g.x + s[t][1] * e1g.y;
        d1b += s[t][2] * e1h.x + s[t][3] * e1h.y;
        d2a += s[t][0] * e2g.x + s[t][1] * e2g.y;
        d2b += s[t][2] * e2h.x + s[t][3] * e2h.y;
    }
    #pragma unroll
    for (int off = 1; off <= 2; off <<= 1) {
        d1a += __shfl_xor_sync(0xffffffffu, d1a, off);
        d1b += __shfl_xor_sync(0xffffffffu, d1b, off);
        d2a += __shfl_xor_sync(0xffffffffu, d2a, off);
        d2b += __shfl_xor_sync(0xffffffffu, d2b, off);
    }
    const float r1a = 1.f / d1a, r1b = 1.f / d1b;
    const float r2a = 1.f / d2a, r2b = 1.f / d2b;

    // all warps done reading K -> safe to overwrite K region with V1
    __syncthreads();
    prefetchV(vA, 1, sbase + SV1);   // G1

    const int vrow_off = (lane & 7) + ((lane & 8) ? 8 : 0);
    const int vcol_off = (lane & 16) ? 8 : 0;

    // per-chunk PV compute: packs P from s-regs, mmas against V buffer
    auto pv_chunk = [&](float o[8][4], const __half* e, float ra, float rb,
                        int chunk, uint32_t vbuf) {
        #pragma unroll
        for (int kk = 0; kk < 4; kk++) {
            const int t0 = chunk * 8 + kk * 2;
            const int ca = t0 * 8 + tg * 2;
            float2 eA = __half22float2(*(const __half2*)(e + ca));
            float2 eB = __half22float2(*(const __half2*)(e + 8 * NDIM + ca));
            float2 eC = __half22float2(*(const __half2*)(e + ca + 8));
            float2 eD = __half22float2(*(const __half2*)(e + 8 * NDIM + ca + 8));
            uint32_t pH[4];
            pH[0] = pack_h2(s[t0][0] * eA.x * ra,     s[t0][1] * eA.y * ra);
            pH[1] = pack_h2(s[t0][2] * eB.x * rb,     s[t0][3] * eB.y * rb);
            pH[2] = pack_h2(s[t0 + 1][0] * eC.x * ra, s[t0 + 1][1] * eC.y * ra);
            pH[3] = pack_h2(s[t0 + 1][2] * eD.x * rb, s[t0 + 1][3] * eD.y * rb);
            const int vrow = kk * 16 + vrow_off;
            #pragma unroll
            for (int dp = 0; dp < 2; dp++) {
                uint32_t b0[4], b1[4];
                ldsm_x4t(b0, vbuf + vrow * 144 + ((2 * dp) * 16 + vcol_off) * 2);
                ldsm_x4t(b1, vbuf + vrow * 144 + ((2 * dp + 1) * 16 + vcol_off) * 2);
                mma16816(o[4 * dp + 0], pH, b0);
                mma16816(o[4 * dp + 1], pH, b0 + 2);
                mma16816(o[4 * dp + 2], pH, b1);
                mma16816(o[4 * dp + 3], pH, b1 + 2);
            }
        }
    };

    // ---- pass A: O1 = softmax(S+b1) @ v_h ----
    {
        float o1[8][4];
        #pragma unroll
        for (int nt = 0; nt < 8; nt++)
            #pragma unroll
            for (int q = 0; q < 4; q++) o1[nt][q] = 0.f;

        CP_WAIT(1); __syncthreads();
        pv_chunk(o1, e1, r1a, r1b, 0, sbase + SV0);
        __syncthreads();
        prefetchV(vA, 2, sbase + SV0);           // G2

        CP_WAIT(1); __syncthreads();
        pv_chunk(o1, e1, r1a, r1b, 1, sbase + SV1);
        __syncthreads();
        prefetchV(vA, 3, sbase + SV1);           // G3

        CP_WAIT(1); __syncthreads();
        pv_chunk(o1, e1, r1a, r1b, 2, sbase + SV0);
        __syncthreads();
        prefetchV(vB, 0, sbase + SV0);           // G4

        CP_WAIT(1); __syncthreads();
        pv_chunk(o1, e1, r1a, r1b, 3, sbase + SV1);
        __syncthreads();
        prefetchV(vB, 1, sbase + SV1);           // G5

        const size_t orow = (size_t)(b * NDIM + n0 + i0 + g);
        #pragma unroll
        for (int nt = 0; nt < 8; nt++) {
            const int col = h * DDIM + nt * 8 + tg * 2;
            *(__half2*)&g_o1[orow * CDIM + col]       = __floats2half2_rn(o1[nt][0], o1[nt][1]);
            *(__half2*)&g_o1[(orow + 8) * CDIM + col] = __floats2half2_rn(o1[nt][2], o1[nt][3]);
        }
    }

    // ---- pass B: O2 = softmax(S+b2) @ v ----
    {
        float o2[8][4];
        #pragma unroll
        for (int nt = 0; nt < 8; nt++)
            #pragma unroll
            for (int q = 0; q < 4; q++) o2[nt][q] = 0.f;

        CP_WAIT(1); __syncthreads();
        pv_chunk(o2, e2, r2a, r2b, 0, sbase + SV0);
        __syncthreads();
        prefetchV(vB, 2, sbase + SV0);           // G6

        CP_WAIT(1); __syncthreads();
        pv_chunk(o2, e2, r2a, r2b, 1, sbase + SV1);
        __syncthreads();
        prefetchV(vB, 3, sbase + SV1);           // G7

        CP_WAIT(1); __syncthreads();
        pv_chunk(o2, e2, r2a, r2b, 2, sbase + SV0);

        CP_WAIT(0); __syncthreads();
        pv_chunk(o2, e2, r2a, r2b, 3, sbase + SV1);

        const size_t orow = (size_t)(b * NDIM + n0 + i0 + g);
        #pragma unroll
        for (int nt = 0; nt < 8; nt++) {
            const int col = h * DDIM + nt * 8 + tg * 2;
            *(__half2*)&g_o2[orow * CDIM + col]       = __floats2half2_rn(o2[nt][0], o2[nt][1]);
            *(__half2*)&g_o2[(orow + 8) * CDIM + col] = __floats2half2_rn(o2[nt][2], o2[nt][3]);
        }
    }
}

// ---------------- launch ----------------
extern "C" void kernel_launch(void* const* d_in, const int* in_sizes, int n_in,
                              void* d_out, int out_size)
{
    const float* x1    = (const float*)d_in[0];
    const float* x2    = (const float*)d_in[1];
    const float* qv_w  = (const float*)d_in[2];
    const float* qv_b  = (const float*)d_in[3];
    const float* kv_w  = (const float*)d_in[4];
    const float* kv_b  = (const float*)d_in[5];
    const float* p1w   = (const float*)d_in[6];
    const float* p1b   = (const float*)d_in[7];
    const float* p2w   = (const float*)d_in[8];
    const float* p2b   = (const float*)d_in[9];
    const float* rpb   = (const float*)d_in[10];
    const float* ppw   = (const float*)d_in[11];
    const float* ppb   = (const float*)d_in[12];
    const float* ln1g  = (const float*)d_in[13];
    const float* ln1b  = (const float*)d_in[14];
    const float* l1w   = (const float*)d_in[15];
    const float* l1b   = (const float*)d_in[16];
    const float* ln2g  = (const float*)d_in[17];
    const float* ln2b  = (const float*)d_in[18];
    const float* l2w   = (const float*)d_in[19];
    const float* l2b   = (const float*)d_in[20];
    const float* ln3g  = (const float*)d_in[21];
    const float* ln3b  = (const float*)d_in[22];
    const float* l3w   = (const float*)d_in[23];
    const float* l3b   = (const float*)d_in[24];
    const int*   rpi   = (const int*)d_in[25];
    float* out = (float*)d_out;

    __half *px1, *px2, *pw1, *pw2, *pqv, *pkv, *po1, *po2;
    cudaGetSymbolAddress((void**)&px1, g_x1);
    cudaGetSymbolAddress((void**)&px2, g_x2);
    cudaGetSymbolAddress((void**)&pw1, g_w1);
    cudaGetSymbolAddress((void**)&pw2, g_w2);
    cudaGetSymbolAddress((void**)&pqv, g_qv);
    cudaGetSymbolAddress((void**)&pkv, g_kv);
    cudaGetSymbolAddress((void**)&po1, g_o1);
    cudaGetSymbolAddress((void**)&po2, g_o2);

    cudaFuncSetAttribute(mma_gemm_kernel,
                         cudaFuncAttributeMaxDynamicSharedMemorySize, GEMM_SMEM);
    cudaFuncSetAttribute(attn_mma_kernel,
                         cudaFuncAttributeMaxDynamicSharedMemorySize, ATTN_SMEM);

    const int X4 = (int)(AELEM / 4);

    // 1) positional MLP + pre-exponentiated fp16 bias tables
    pos_mlp_kernel<<<4, 256>>>(ppw, ppb, ln1g, ln1b, l1w, l1b,
                               ln2g, ln2b, l2w, l2b, ln3g, ln3b, l3w, l3b);
    bias_build_kernel<<<(NHH * NDIM * NDIM) / 256, 256>>>(rpi, rpb);

    // 2) converts (both inputs, both QV/KV weights)
    conv2_kernel<<<dim3(X4 / 256, 2), 256>>>(x1, x2, px1, px2, X4);
    wconvT2_kernel<<<dim3((TWOC * KDIM) / 256, 2), 256>>>(qv_w, kv_w, pw1, pw2, TWOC);

    // 3) fused QV+KV projections (grid.z selects problem)
    mma_gemm_kernel<<<dim3(TWOC / 128, MROWS / 128, 2), 256, GEMM_SMEM>>>(
        px1, px2, pw1, pw2, qv_b, kv_b, nullptr, nullptr, pqv, pkv, TWOC, 1);

    // 4) fp16 tensor-core dual-softmax attention (V cp.async double-buffered)
    attn_mma_kernel<<<dim3(NDIM / 128, NHH, BDIM), 256, ATTN_SMEM>>>();

    // 5) fused output projections into d_out (fp32)
    wconvT2_kernel<<<dim3((CDIM * KDIM) / 256, 2), 256>>>(p1w, p2w, pw1, pw2, CDIM);
    mma_gemm_kernel<<<dim3(CDIM / 128, MROWS / 128, 2), 256, GEMM_SMEM>>>(
        po1, po2, pw1, pw2, p1b, p2b, out, out + AELEM, nullptr, nullptr, CDIM, 0);
}

// round 17
// speedup vs baseline: 2.2507x; 1.0846x over previous
#include <cuda_runtime.h>
#include <cuda_fp16.h>
#include <cstdint>

// Problem constants
#define BDIM  128
#define NDIM  256
#define CDIM  384
#define NHH   6
#define DDIM  64
#define TWOC  768
#define NPOS  961
#define KDIM  384                    // GEMM K (== CDIM) for all projections
#define NKSTEPS 12                   // KDIM / 32, compile-time
#define MROWS (BDIM * NDIM)          // 32768
#define AELEM ((size_t)MROWS * CDIM) // 12,582,912

// ---------------- device scratch ----------------
__device__ __half g_b1[(size_t)NHH * NDIM * NDIM];   // exp(bias1)[h][n][m], fp16
__device__ __half g_b2[(size_t)NHH * NDIM * NDIM];   // exp(bias2)[h][n][m], fp16
__device__ float  g_pos[NPOS * NHH];

// fp16 buffers (single precision products, fp32 accumulate)
__device__ __half g_x1[AELEM], g_x2[AELEM];
__device__ __half g_w1[CDIM * TWOC], g_w2[CDIM * TWOC];  // weights TRANSPOSED [Nc][K]
__device__ __half g_qv[(size_t)MROWS * TWOC];
__device__ __half g_kv[(size_t)MROWS * TWOC];
__device__ __half g_o1[AELEM], g_o2[AELEM];

// ---------------- low-level helpers ----------------
__device__ __forceinline__ void cpa16(uint32_t dst, const void* src) {
    asm volatile("cp.async.cg.shared.global [%0], [%1], 16;\n"
                 :: "r"(dst), "l"(src));
}
#define CP_COMMIT() asm volatile("cp.async.commit_group;\n")
#define CP_WAIT(n)  asm volatile("cp.async.wait_group %0;\n" :: "n"(n))

__device__ __forceinline__ void ldsm_x4(uint32_t* r, uint32_t a) {
    asm volatile("ldmatrix.sync.aligned.m8n8.x4.shared.b16 {%0,%1,%2,%3}, [%4];\n"
                 : "=r"(r[0]), "=r"(r[1]), "=r"(r[2]), "=r"(r[3]) : "r"(a));
}
__device__ __forceinline__ void ldsm_x4t(uint32_t* r, uint32_t a) {
    asm volatile("ldmatrix.sync.aligned.m8n8.x4.trans.shared.b16 {%0,%1,%2,%3}, [%4];\n"
                 : "=r"(r[0]), "=r"(r[1]), "=r"(r[2]), "=r"(r[3]) : "r"(a));
}
__device__ __forceinline__ void mma16816(float* c, const uint32_t* a,
                                         const uint32_t* b) {
    asm volatile(
        "mma.sync.aligned.m16n8k16.row.col.f32.f16.f16.f32 "
        "{%0,%1,%2,%3}, {%4,%5,%6,%7}, {%8,%9}, {%0,%1,%2,%3};\n"
        : "+f"(c[0]), "+f"(c[1]), "+f"(c[2]), "+f"(c[3])
        : "r"(a[0]), "r"(a[1]), "r"(a[2]), "r"(a[3]), "r"(b[0]), "r"(b[1]));
}
__device__ __forceinline__ uint32_t pack_h2(float a, float b) {
    __half2 h = __floats2half2_rn(a, b);   // .x = a (low half)
    return *reinterpret_cast<uint32_t*>(&h);
}
__device__ __forceinline__ uint32_t hmul2u(uint32_t a, uint32_t b) {
    __half2 r = __hmul2(*reinterpret_cast<__half2*>(&a),
                        *reinterpret_cast<__half2*>(&b));
    return *reinterpret_cast<uint32_t*>(&r);
}

// ---------------- tiny positional MLP ----------------
__device__ __forceinline__ void ln_relu24(const float* x, const float* g,
                                          const float* b, float* y) {
    float m = 0.f;
    #pragma unroll
    for (int p = 0; p < 24; p++) m += x[p];
    m *= (1.f / 24.f);
    float v = 0.f;
    #pragma unroll
    for (int p = 0; p < 24; p++) { float d = x[p] - m; v += d * d; }
    v *= (1.f / 24.f);
    float rs = rsqrtf(v + 1e-5f);
    #pragma unroll
    for (int p = 0; p < 24; p++) {
        float val = (x[p] - m) * rs * g[p] + b[p];
        y[p] = fmaxf(val, 0.f);
    }
}

__global__ void pos_mlp_kernel(
    const float* __restrict__ ppw, const float* __restrict__ ppb,
    const float* __restrict__ g1, const float* __restrict__ b1,
    const float* __restrict__ w1, const float* __restrict__ wb1,
    const float* __restrict__ g2, const float* __restrict__ b2,
    const float* __restrict__ w2, const float* __restrict__ wb2,
    const float* __restrict__ g3, const float* __restrict__ b3,
    const float* __restrict__ w3, const float* __restrict__ wb3)
{
    int r = blockIdx.x * blockDim.x + threadIdx.x;
    if (r >= NPOS) return;
    float ph = (float)(r / 31 - 15);
    float pw = (float)(r % 31 - 15);
    float t[24], u[24], t2[24];
    #pragma unroll
    for (int p = 0; p < 24; p++) t[p] = ph * ppw[p] + pw * ppw[24 + p] + ppb[p];
    ln_relu24(t, g1, b1, u);
    for (int q = 0; q < 24; q++) {
        float a = wb1[q];
        for (int p = 0; p < 24; p++) a += u[p] * w1[p * 24 + q];
        t2[q] = a;
    }
    ln_relu24(t2, g2, b2, u);
    for (int q = 0; q < 24; q++) {
        float a = wb2[q];
        for (int p = 0; p < 24; p++) a += u[p] * w2[p * 24 + q];
        t[q] = a;
    }
    ln_relu24(t, g3, b3, u);
    for (int q = 0; q < NHH; q++) {
        float a = wb3[q];
        for (int p = 0; p < 24; p++) a += u[p] * w3[p * NHH + q];
        g_pos[r * NHH + q] = a;
    }
}

// ---------------- bias tables (pre-exponentiated, fp16) ----------------
__global__ void bias_build_kernel(const int* __restrict__ rpi,
                                  const float* __restrict__ rpb)
{
    int t = blockIdx.x * blockDim.x + threadIdx.x;
    int h  = t >> 16;
    int nm = t & 65535;
    int r = rpi[nm];
    g_b1[t] = __float2half(__expf(rpb[r * NHH + h]));
    g_b2[t] = __float2half(__expf(g_pos[r * NHH + h]));
}

// ---------------- fp32 -> fp16 convert (dual input via grid.y) ----------------
__global__ void conv2_kernel(const float* __restrict__ xa,
                             const float* __restrict__ xb,
                             __half* __restrict__ ya,
                             __half* __restrict__ yb, int n4)
{
    int i = blockIdx.x * blockDim.x + threadIdx.x;
    if (i >= n4) return;
    const float* x = blockIdx.y ? xb : xa;
    __half* y = blockIdx.y ? yb : ya;
    float4 v = ((const float4*)x)[i];
    ((__half2*)y)[2 * i]     = __floats2half2_rn(v.x, v.y);
    ((__half2*)y)[2 * i + 1] = __floats2half2_rn(v.z, v.w);
}

// ---------------- dual weight transpose-convert: W[K][Nc] -> Wt [Nc][K] ----------------
__global__ void wconvT2_kernel(const float* __restrict__ Wa,
                               const float* __restrict__ Wb,
                               __half* __restrict__ ya,
                               __half* __restrict__ yb, int Nc)
{
    int t = blockIdx.x * blockDim.x + threadIdx.x;   // t = n*K + k
    int n = t / KDIM, k = t - n * KDIM;
    const float* W = blockIdx.y ? Wb : Wa;
    __half* y = blockIdx.y ? yb : ya;
    y[t] = __float2half(W[(size_t)k * Nc + n]);
}

// ---------------- fp16 tensor-core GEMM (dual problem via grid.z, 3-stage) ----------------
#define TILE_B 10240                     // bytes per tile (128 * 40 halves * 2)
#define STAGE_B (2 * TILE_B)             // 20480 bytes per stage
#define GEMM_SMEM (3 * STAGE_B)          // 61440 bytes (3 stages)

__global__ __launch_bounds__(256, 2) void mma_gemm_kernel(
    const __half* __restrict__ A0, const __half* __restrict__ A1,
    const __half* __restrict__ B0T, const __half* __restrict__ B1T,
    const float* __restrict__ bias0, const float* __restrict__ bias1,
    float* __restrict__ Cf0, float* __restrict__ Cf1,
    __half* __restrict__ Ch0, __half* __restrict__ Ch1,
    int Nc, int halfOut)
{
    extern __shared__ __half sh[];
    const uint32_t sbase = (uint32_t)__cvta_generic_to_shared(sh);
    const int z = blockIdx.z;
    const __half* A  = z ? A1  : A0;
    const __half* BT = z ? B1T : B0T;
    const float* bias = z ? bias1 : bias0;
    float* Cf = z ? Cf1 : Cf0;
    __half* Ch = z ? Ch1 : Ch0;

    const int tid = threadIdx.x;
    const int lane = tid & 31;
    const int wid = tid >> 5;
    const int wm = wid >> 2;          // 0..1
    const int wn = wid & 3;           // 0..3
    const int rowBase = blockIdx.y * 128;
    const int colBase = blockIdx.x * 128;

    auto load_stage = [&](int s, int kt) {
        const int k0 = kt * 32;
        const uint32_t stg = sbase + s * STAGE_B;
        #pragma unroll
        for (int j = 0; j < 4; j++) {
            int idx = tid + j * 256;          // 0..1023
            int tile = idx >> 9;              // 0:A 1:BT
            int within = idx & 511;
            int row = within >> 2;            // 0..127
            int c8 = within & 3;              // 0..3 (8-half chunks)
            uint32_t dst = stg + tile * TILE_B + row * 80 + c8 * 16;
            const __half* src = (tile == 0)
                ? A  + (size_t)(rowBase + row) * KDIM + k0 + c8 * 8
                : BT + (size_t)(colBase + row) * KDIM + k0 + c8 * 8;
            cpa16(dst, src);
        }
        CP_COMMIT();
    };

    load_stage(0, 0);
    load_stage(1, 1);
    load_stage(2, 2);

    float acc[4][4][4] = {};

    const int bro = ((lane >> 4) << 3) + (lane & 7);
    const int bco = ((lane >> 3) & 1) * 8;

    int s = 0;
    #pragma unroll 1
    for (int kt = 0; kt < NKSTEPS; kt++) {
        if (kt + 2 < NKSTEPS)      CP_WAIT(2);
        else if (kt + 1 < NKSTEPS) CP_WAIT(1);
        else                       CP_WAIT(0);
        __syncthreads();
        const uint32_t stg = sbase + s * STAGE_B;
        #pragma unroll
        for (int k16 = 0; k16 < 2; k16++) {
            uint32_t bfr[2][4];
            #pragma unroll
            for (int np = 0; np < 2; np++) {
                uint32_t ba = stg + TILE_B +
                              (uint32_t)(wn * 32 + np * 16 + bro) * 80 +
                              (uint32_t)(k16 * 16 + bco) * 2;
                ldsm_x4(bfr[np], ba);
            }
            const int acol = k16 * 16 + ((lane >> 4) << 3);
            #pragma unroll
            for (int mt = 0; mt < 4; mt++) {
                const int arow = wm * 64 + mt * 16 + (lane & 15);
                uint32_t a[4];
                ldsm_x4(a, stg + (uint32_t)arow * 80 + (uint32_t)acol * 2);
                #pragma unroll
                for (int nt = 0; nt < 4; nt++)
                    mma16816(acc[mt][nt], a, &bfr[nt >> 1][(nt & 1) * 2]);
            }
        }
        __syncthreads();
        if (kt + 3 < NKSTEPS) load_stage(s, kt + 3);
        s = (s == 2) ? 0 : s + 1;
    }

    const int g = lane >> 2, tg = lane & 3;
    #pragma unroll
    for (int mt = 0; mt < 4; mt++) {
        const int r0 = rowBase + wm * 64 + mt * 16 + g;
        #pragma unroll
        for (int nt = 0; nt < 4; nt++) {
            const int c0 = colBase + wn * 32 + nt * 8 + tg * 2;
            const float b0 = bias[c0], b1 = bias[c0 + 1];
            float v0 = acc[mt][nt][0] + b0, v1 = acc[mt][nt][1] + b1;
            float v2 = acc[mt][nt][2] + b0, v3 = acc[mt][nt][3] + b1;
            if (halfOut) {
                *(__half2*)&Ch[(size_t)r0 * Nc + c0]       = __floats2half2_rn(v0, v1);
                *(__half2*)&Ch[(size_t)(r0 + 8) * Nc + c0] = __floats2half2_rn(v2, v3);
            } else {
                float2 lo = { v0, v1 };
                float2 hi = { v2, v3 };
                *(float2*)&Cf[(size_t)r0 * Nc + c0]       = lo;
                *(float2*)&Cf[(size_t)(r0 + 8) * Nc + c0] = hi;
            }
        }
    }
}

// ---------------- fp16 tensor-core dual-softmax attention ----------------
// Denominators via all-ones B-fragment mma (ΣP̃ in fp32 accumulators);
// O normalized at the end. P̃ built from packed half2 exp(S) via one HMUL2.
#define SQ 0
#define SK 18432
#define SV1 18432
#define SV0 55296
#define ATTN_SMEM 64512
#define ONES_H2 0x3C003C00u

__global__ __launch_bounds__(256, 1) void attn_mma_kernel()
{
    extern __shared__ char sm[];
    const uint32_t sbase = (uint32_t)__cvta_generic_to_shared(sm);
    const int b = blockIdx.z, h = blockIdx.y, n0 = blockIdx.x * 128;
    const int tid = threadIdx.x;
    const int lane = tid & 31;
    const int wid = tid >> 5;
    const int g = lane >> 2, tg = lane & 3;
    const int i0 = wid * 16;

    const __half* vA = g_kv + ((size_t)(b * NDIM)) * TWOC + CDIM + h * DDIM; // v_h
    const __half* vB = g_qv + ((size_t)(b * NDIM)) * TWOC + CDIM + h * DDIM; // v

    auto prefetchV = [&](const __half* vsrc, int chunk, uint32_t dst) {
        #pragma unroll
        for (int rep = 0; rep < 2; rep++) {
            int idx = tid + rep * 256;        // 0..511
            int r = idx >> 3, c = idx & 7;
            cpa16(dst + (uint32_t)(r * 144 + c * 16),
                  vsrc + (size_t)(chunk * 64 + r) * TWOC + c * 8);
        }
        CP_COMMIT();
    };

    // G0: pass-A chunk 0 into V0 (region disjoint from Q/K)
    prefetchV(vA, 0, sbase + SV0);

    {
        const __half* q = g_qv + ((size_t)(b * NDIM + n0)) * TWOC + h * DDIM;
        for (int idx = tid; idx < 1024; idx += 256) {
            int r = idx >> 3, c = idx & 7;
            *(uint4*)(sm + SQ + r * 144 + c * 16) = *(const uint4*)(q + (size_t)r * TWOC + c * 8);
        }
        const __half* k = g_kv + ((size_t)(b * NDIM)) * TWOC + h * DDIM;
        for (int idx = tid; idx < 2048; idx += 256) {
            int r = idx >> 3, c = idx & 7;
            *(uint4*)(sm + SK + r * 144 + c * 16) = *(const uint4*)(k + (size_t)r * TWOC + c * 8);
        }
    }
    __syncthreads();

    float s[32][4];
    #pragma unroll
    for (int t = 0; t < 32; t++)
        #pragma unroll
        for (int q = 0; q < 4; q++) s[t][q] = 0.f;

    const int arow = i0 + (lane & 15);
    const int krow_off = (lane & 7) + ((lane & 16) ? 8 : 0);
    #pragma unroll
    for (int d0 = 0; d0 < 64; d0 += 16) {
        uint32_t a[4];
        const int acol = d0 + ((lane & 16) ? 8 : 0);
        ldsm_x4(a, sbase + SQ + arow * 144 + acol * 2);
        const int kcol = d0 + ((lane & 8) ? 8 : 0);
        #pragma unroll
        for (int jp = 0; jp < 8; jp++) {
            uint32_t b0[4], b1[4];
            ldsm_x4(b0, sbase + SK + ((2 * jp) * 16 + krow_off) * 144 + kcol * 2);
            ldsm_x4(b1, sbase + SK + ((2 * jp + 1) * 16 + krow_off) * 144 + kcol * 2);
            mma16816(s[4 * jp + 0], a, b0);
            mma16816(s[4 * jp + 1], a, b0 + 2);
            mma16816(s[4 * jp + 2], a, b1);
            mma16816(s[4 * jp + 3], a, b1 + 2);
        }
    }

    // exp(S*scale) packed to half2: sh2[t][0]=cols(c,c+1) row g ; [1]=row g+8
    uint32_t sh2[32][2];
    #pragma unroll
    for (int t = 0; t < 32; t++) {
        float e0 = __expf(s[t][0] * 0.125f);
        float e1 = __expf(s[t][1] * 0.125f);
        float e2 = __expf(s[t][2] * 0.125f);
        float e3 = __expf(s[t][3] * 0.125f);
        sh2[t][0] = pack_h2(e0, e1);
        sh2[t][1] = pack_h2(e2, e3);
    }

    const int rowg = n0 + i0 + g;
    const __half* e1p = g_b1 + ((size_t)h * NDIM + rowg) * NDIM;
    const __half* e2p = g_b2 + ((size_t)h * NDIM + rowg) * NDIM;

    // all warps done reading K -> safe to overwrite K region with V1
    __syncthreads();
    prefetchV(vA, 1, sbase + SV1);   // G1

    const int vrow_off = (lane & 7) + ((lane & 8) ? 8 : 0);
    const int vcol_off = (lane & 16) ? 8 : 0;
    const uint32_t onesB[2] = { ONES_H2, ONES_H2 };

    // per-chunk PV compute: P̃ = sh2*eb (half2), mma against V + ones-mma for ΣP̃
    auto pv_chunk = [&](float o[8][4], float* dacc, const __half* e,
                        int chunk, uint32_t vbuf) {
        #pragma unroll
        for (int kk = 0; kk < 4; kk++) {
            const int t0 = chunk * 8 + kk * 2;
            const int ca = t0 * 8 + tg * 2;
            uint32_t pH[4];
            pH[0] = hmul2u(sh2[t0][0],     *(const uint32_t*)(e + ca));
            pH[1] = hmul2u(sh2[t0][1],     *(const uint32_t*)(e + 8 * NDIM + ca));
            pH[2] = hmul2u(sh2[t0 + 1][0], *(const uint32_t*)(e + ca + 8));
            pH[3] = hmul2u(sh2[t0 + 1][1], *(const uint32_t*)(e + 8 * NDIM + ca + 8));
            const int vrow = kk * 16 + vrow_off;
            mma16816(dacc, pH, onesB);   // row-sum accumulation
            #pragma unroll
            for (int dp = 0; dp < 2; dp++) {
                uint32_t b0[4], b1[4];
                ldsm_x4t(b0, vbuf + vrow * 144 + ((2 * dp) * 16 + vcol_off) * 2);
                ldsm_x4t(b1, vbuf + vrow * 144 + ((2 * dp + 1) * 16 + vcol_off) * 2);
                mma16816(o[4 * dp + 0], pH, b0);
                mma16816(o[4 * dp + 1], pH, b0 + 2);
                mma16816(o[4 * dp + 2], pH, b1);
                mma16816(o[4 * dp + 3], pH, b1 + 2);
            }
        }
    };

    // ---- pass A: O1 = softmax(S+b1) @ v_h ----
    {
        float o1[8][4];
        float d1[4] = {0.f, 0.f, 0.f, 0.f};
        #pragma unroll
        for (int nt = 0; nt < 8; nt++)
            #pragma unroll
            for (int q = 0; q < 4; q++) o1[nt][q] = 0.f;

        CP_WAIT(1); __syncthreads();
        pv_chunk(o1, d1, e1p, 0, sbase + SV0);
        __syncthreads();
        prefetchV(vA, 2, sbase + SV0);           // G2

        CP_WAIT(1); __syncthreads();
        pv_chunk(o1, d1, e1p, 1, sbase + SV1);
        __syncthreads();
        prefetchV(vA, 3, sbase + SV1);           // G3

        CP_WAIT(1); __syncthreads();
        pv_chunk(o1, d1, e1p, 2, sbase + SV0);
        __syncthreads();
        prefetchV(vB, 0, sbase + SV0);           // G4

        CP_WAIT(1); __syncthreads();
        pv_chunk(o1, d1, e1p, 3, sbase + SV1);
        __syncthreads();
        prefetchV(vB, 1, sbase + SV1);           // G5

        const float ra = 1.f / d1[0];   // row g
        const float rb = 1.f / d1[2];   // row g+8
        const size_t orow = (size_t)(b * NDIM + n0 + i0 + g);
        #pragma unroll
        for (int nt = 0; nt < 8; nt++) {
            const int col = h * DDIM + nt * 8 + tg * 2;
            *(__half2*)&g_o1[orow * CDIM + col] =
                __floats2half2_rn(o1[nt][0] * ra, o1[nt][1] * ra);
            *(__half2*)&g_o1[(orow + 8) * CDIM + col] =
                __floats2half2_rn(o1[nt][2] * rb, o1[nt][3] * rb);
        }
    }

    // ---- pass B: O2 = softmax(S+b2) @ v ----
    {
        float o2[8][4];
        float d2[4] = {0.f, 0.f, 0.f, 0.f};
        #pragma unroll
        for (int nt = 0; nt < 8; nt++)
            #pragma unroll
            for (int q = 0; q < 4; q++) o2[nt][q] = 0.f;

        CP_WAIT(1); __syncthreads();
        pv_chunk(o2, d2, e2p, 0, sbase + SV0);
        __syncthreads();
        prefetchV(vB, 2, sbase + SV0);           // G6

        CP_WAIT(1); __syncthreads();
        pv_chunk(o2, d2, e2p, 1, sbase + SV1);
        __syncthreads();
        prefetchV(vB, 3, sbase + SV1);           // G7

        CP_WAIT(1); __syncthreads();
        pv_chunk(o2, d2, e2p, 2, sbase + SV0);

        CP_WAIT(0); __syncthreads();
        pv_chunk(o2, d2, e2p, 3, sbase + SV1);

        const float ra = 1.f / d2[0];
        const float rb = 1.f / d2[2];
        const size_t orow = (size_t)(b * NDIM + n0 + i0 + g);
        #pragma unroll
        for (int nt = 0; nt < 8; nt++) {
            const int col = h * DDIM + nt * 8 + tg * 2;
            *(__half2*)&g_o2[orow * CDIM + col] =
                __floats2half2_rn(o2[nt][0] * ra, o2[nt][1] * ra);
            *(__half2*)&g_o2[(orow + 8) * CDIM + col] =
                __floats2half2_rn(o2[nt][2] * rb, o2[nt][3] * rb);
        }
    }
}

// ---------------- launch ----------------
extern "C" void kernel_launch(void* const* d_in, const int* in_sizes, int n_in,
                              void* d_out, int out_size)
{
    const float* x1    = (const float*)d_in[0];
    const float* x2    = (const float*)d_in[1];
    const float* qv_w  = (const float*)d_in[2];
    const float* qv_b  = (const float*)d_in[3];
    const float* kv_w  = (const float*)d_in[4];
    const float* kv_b  = (const float*)d_in[5];
    const float* p1w   = (const float*)d_in[6];
    const float* p1b   = (const float*)d_in[7];
    const float* p2w   = (const float*)d_in[8];
    const float* p2b   = (const float*)d_in[9];
    const float* rpb   = (const float*)d_in[10];
    const float* ppw   = (const float*)d_in[11];
    const float* ppb   = (const float*)d_in[12];
    const float* ln1g  = (const float*)d_in[13];
    const float* ln1b  = (const float*)d_in[14];
    const float* l1w   = (const float*)d_in[15];
    const float* l1b   = (const float*)d_in[16];
    const float* ln2g  = (const float*)d_in[17];
    const float* ln2b  = (const float*)d_in[18];
    const float* l2w   = (const float*)d_in[19];
    const float* l2b   = (const float*)d_in[20];
    const float* ln3g  = (const float*)d_in[21];
    const float* ln3b  = (const float*)d_in[22];
    const float* l3w   = (const float*)d_in[23];
    const float* l3b   = (const float*)d_in[24];
    const int*   rpi   = (const int*)d_in[25];
    float* out = (float*)d_out;

    __half *px1, *px2, *pw1, *pw2, *pqv, *pkv, *po1, *po2;
    cudaGetSymbolAddress((void**)&px1, g_x1);
    cudaGetSymbolAddress((void**)&px2, g_x2);
    cudaGetSymbolAddress((void**)&pw1, g_w1);
    cudaGetSymbolAddress((void**)&pw2, g_w2);
    cudaGetSymbolAddress((void**)&pqv, g_qv);
    cudaGetSymbolAddress((void**)&pkv, g_kv);
    cudaGetSymbolAddress((void**)&po1, g_o1);
    cudaGetSymbolAddress((void**)&po2, g_o2);

    cudaFuncSetAttribute(mma_gemm_kernel,
                         cudaFuncAttributeMaxDynamicSharedMemorySize, GEMM_SMEM);
    cudaFuncSetAttribute(attn_mma_kernel,
                         cudaFuncAttributeMaxDynamicSharedMemorySize, ATTN_SMEM);

    const int X4 = (int)(AELEM / 4);

    // 1) positional MLP + pre-exponentiated fp16 bias tables
    pos_mlp_kernel<<<4, 256>>>(ppw, ppb, ln1g, ln1b, l1w, l1b,
                               ln2g, ln2b, l2w, l2b, ln3g, ln3b, l3w, l3b);
    bias_build_kernel<<<(NHH * NDIM * NDIM) / 256, 256>>>(rpi, rpb);

    // 2) converts (both inputs, both QV/KV weights)
    conv2_kernel<<<dim3(X4 / 256, 2), 256>>>(x1, x2, px1, px2, X4);
    wconvT2_kernel<<<dim3((TWOC * KDIM) / 256, 2), 256>>>(qv_w, kv_w, pw1, pw2, TWOC);

    // 3) fused QV+KV projections (grid.z selects problem)
    mma_gemm_kernel<<<dim3(TWOC / 128, MROWS / 128, 2), 256, GEMM_SMEM>>>(
        px1, px2, pw1, pw2, qv_b, kv_b, nullptr, nullptr, pqv, pkv, TWOC, 1);

    // 4) attention (ones-mma denominators, half2 P path)
    attn_mma_kernel<<<dim3(NDIM / 128, NHH, BDIM), 256, ATTN_SMEM>>>();

    // 5) fused output projections into d_out (fp32)
    wconvT2_kernel<<<dim3((CDIM * KDIM) / 256, 2), 256>>>(p1w, p2w, pw1, pw2, CDIM);
    mma_gemm_kernel<<<dim3(CDIM / 128, MROWS / 128, 2), 256, GEMM_SMEM>>>(
        po1, po2, pw1, pw2, p1b, p2b, out, out + AELEM, nullptr, nullptr, CDIM, 0);
}